// round 11
// baseline (speedup 1.0000x reference)
#include <cuda_runtime.h>
#include <cuda_bf16.h>
#include <cstdint>
#include <math.h>

#define TT 2048
#define DM 2048
#define NH 16
#define DH 128

// ===================== PTX helpers ==========================================
__device__ __forceinline__ uint32_t smem_u32(const void* p) {
    uint32_t a;
    asm("{ .reg .u64 t; cvta.to.shared.u64 t, %1; cvt.u32.u64 %0, t; }"
        : "=r"(a) : "l"(p));
    return a;
}

#define CPASYNC16(dst, src) \
    asm volatile("cp.async.cg.shared.global [%0], [%1], 16;" :: "r"(dst), "l"(src))
#define CP_COMMIT() asm volatile("cp.async.commit_group;" ::: "memory")
#define CP_WAIT0() asm volatile("cp.async.wait_group 0;" ::: "memory")
#define CP_WAIT1() asm volatile("cp.async.wait_group 1;" ::: "memory")

#define LDMAT_X4(r0, r1, r2, r3, addr) \
    asm volatile("ldmatrix.sync.aligned.m8n8.x4.shared.b16 {%0,%1,%2,%3}, [%4];" \
                 : "=r"(r0), "=r"(r1), "=r"(r2), "=r"(r3) : "r"(addr))
#define LDMAT_X2_T(b0, b1, addr) \
    asm volatile("ldmatrix.sync.aligned.m8n8.x2.trans.shared.b16 {%0,%1}, [%2];" \
                 : "=r"(b0), "=r"(b1) : "r"(addr))

__device__ __forceinline__ void mma_bf16(float* c, uint32_t a0, uint32_t a1,
                                         uint32_t a2, uint32_t a3,
                                         uint32_t b0, uint32_t b1) {
    asm volatile(
        "mma.sync.aligned.m16n8k16.row.col.f32.bf16.bf16.f32 "
        "{%0,%1,%2,%3}, {%4,%5,%6,%7}, {%8,%9}, {%0,%1,%2,%3};"
        : "+f"(c[0]), "+f"(c[1]), "+f"(c[2]), "+f"(c[3])
        : "r"(a0), "r"(a1), "r"(a2), "r"(a3), "r"(b0), "r"(b1));
}

__device__ __forceinline__ uint32_t pack_bf16(float a, float b) {
    __nv_bfloat162 t = __floats2bfloat162_rn(a, b);
    return *(uint32_t*)&t;
}

// ===================== scratch (static device globals) =======================
__device__ __nv_bfloat16 g_hh[(size_t)TT * DM], g_hl[(size_t)TT * DM];
__device__ __nv_bfloat16 g_ath[(size_t)TT * DM], g_atl[(size_t)TT * DM];
__device__ __nv_bfloat16 g_qh[(size_t)TT * DM], g_ql[(size_t)TT * DM];
__device__ __nv_bfloat16 g_kh[(size_t)TT * DM], g_kl[(size_t)TT * DM];
__device__ __nv_bfloat16 g_vh[(size_t)TT * DM], g_vl[(size_t)TT * DM];
__device__ __nv_bfloat16 g_wqh[(size_t)DM * DM], g_wql[(size_t)DM * DM];
__device__ __nv_bfloat16 g_wkh[(size_t)DM * DM], g_wkl[(size_t)DM * DM];
__device__ __nv_bfloat16 g_wvh[(size_t)DM * DM], g_wvl[(size_t)DM * DM];
__device__ __nv_bfloat16 g_woh[(size_t)DM * DM], g_wol[(size_t)DM * DM];

// ===================== fused split of all 4 weights ==========================
__global__ __launch_bounds__(256) void split_all_kernel(
    const float* __restrict__ wq, const float* __restrict__ wk,
    const float* __restrict__ wv, const float* __restrict__ wo) {
    const int w = blockIdx.x >> 12;
    const int blk = blockIdx.x & 4095;
    const float* X = (w == 0) ? wq : (w == 1) ? wk : (w == 2) ? wv : wo;
    __nv_bfloat16* Hi = (w == 0) ? g_wqh : (w == 1) ? g_wkh : (w == 2) ? g_wvh : g_woh;
    __nv_bfloat16* Lo = (w == 0) ? g_wql : (w == 1) ? g_wkl : (w == 2) ? g_wvl : g_wol;

    const int i = (blk * 256 + threadIdx.x) * 4;
    float4 v = *(const float4*)(X + i);
    float f[4] = {v.x, v.y, v.z, v.w};
    unsigned short hb[4], lb[4];
#pragma unroll
    for (int j = 0; j < 4; j++) {
        __nv_bfloat16 h = __float2bfloat16(f[j]);
        __nv_bfloat16 l = __float2bfloat16(f[j] - __bfloat162float(h));
        hb[j] = __bfloat16_as_ushort(h);
        lb[j] = __bfloat16_as_ushort(l);
    }
    uint2 hv, lv;
    hv.x = (uint32_t)hb[0] | ((uint32_t)hb[1] << 16);
    hv.y = (uint32_t)hb[2] | ((uint32_t)hb[3] << 16);
    lv.x = (uint32_t)lb[0] | ((uint32_t)lb[1] << 16);
    lv.y = (uint32_t)lb[2] | ((uint32_t)lb[3] << 16);
    *(uint2*)(Hi + i) = hv;
    *(uint2*)(Lo + i) = lv;
}

// ===================== RMSNorm (emits bf16 hi/lo) ============================
__global__ __launch_bounds__(256) void rmsnorm_kernel(const float* __restrict__ x,
                                                      const float* __restrict__ w) {
    __shared__ float red[256];
    const int row = blockIdx.x;
    const int tid = threadIdx.x;
    const float* xr = x + (size_t)row * DM;
    float s = 0.f;
    for (int i = tid; i < DM; i += 256) { float v = xr[i]; s += v * v; }
    red[tid] = s;
    __syncthreads();
    for (int o = 128; o > 0; o >>= 1) {
        if (tid < o) red[tid] += red[tid + o];
        __syncthreads();
    }
    const float inv = rsqrtf(red[0] / (float)DM + 1e-5f);
    __nv_bfloat16* hh = g_hh + (size_t)row * DM;
    __nv_bfloat16* hl = g_hl + (size_t)row * DM;
    for (int i = tid; i < DM; i += 256) {
        float y = w[i] * xr[i] * inv;
        __nv_bfloat16 h = __float2bfloat16(y);
        hh[i] = h;
        hl[i] = __float2bfloat16(y - __bfloat162float(h));
    }
}

// ===================== shared GEMM machinery =================================
// CTA tile 128(M) x 256(N), BK=32, 8 warps in 2(M)x4(N) -> warp tile 64x64.
#define SPAD 40
#define EA_L (128 * SPAD)        // elem offsets inside a stage
#define EB_H (256 * SPAD)
#define EB_L (512 * SPAD)
#define STG_E (768 * SPAD)       // stage elems
#define GEMM_SMEM (2 * STG_E * 2)  // 122880 bytes
#define SROW 132                 // fp32 epilogue staging row stride

__device__ __forceinline__ void gemm_load_stage(
    uint32_t sbase, int st,
    const __nv_bfloat16* Ah, const __nv_bfloat16* Al,
    const __nv_bfloat16* Bh, const __nv_bfloat16* Bl,
    int m0, int n0, int k0, int tid) {
    const uint32_t sb = sbase + (uint32_t)(st * STG_E) * 2;
    const __nv_bfloat16* pAh = Ah + (size_t)m0 * DM + k0;
    const __nv_bfloat16* pAl = Al + (size_t)m0 * DM + k0;
    const __nv_bfloat16* pBh = Bh + (size_t)n0 * DM + k0;
    const __nv_bfloat16* pBl = Bl + (size_t)n0 * DM + k0;
    // A tiles: 128 rows x 4 chunks = 512 loads each
#pragma unroll
    for (int i = 0; i < 2; i++) {
        const int idx = i * 256 + tid;
        const int r = idx >> 2, c = idx & 3;
        CPASYNC16(sb + (uint32_t)(r * SPAD + c * 8) * 2, pAh + (size_t)r * DM + c * 8);
        CPASYNC16(sb + (uint32_t)(EA_L + r * SPAD + c * 8) * 2, pAl + (size_t)r * DM + c * 8);
    }
    // B tiles: 256 rows x 4 chunks = 1024 loads each
#pragma unroll
    for (int i = 0; i < 4; i++) {
        const int idx = i * 256 + tid;
        const int r = idx >> 2, c = idx & 3;
        CPASYNC16(sb + (uint32_t)(EB_H + r * SPAD + c * 8) * 2, pBh + (size_t)r * DM + c * 8);
        CPASYNC16(sb + (uint32_t)(EB_L + r * SPAD + c * 8) * 2, pBl + (size_t)r * DM + c * 8);
    }
}

// mainloop: acc[4][8][4], sequenced products (hh, hl, lh) to cap live regs.
__device__ __forceinline__ void gemm_mainloop(
    uint32_t sbase, const __nv_bfloat16* Ah, const __nv_bfloat16* Al,
    const __nv_bfloat16* Bh, const __nv_bfloat16* Bl,
    int m0, int n0, int tid, int wm, int wn,
    int a_row, int a_colp, int b_row, int b_ntp, int b_colp,
    float acc[4][8][4]) {
    gemm_load_stage(sbase, 0, Ah, Al, Bh, Bl, m0, n0, 0, tid);
    CP_COMMIT();

    for (int c = 0; c < DM / 32; c++) {
        CP_WAIT0();
        __syncthreads();
        if (c + 1 < DM / 32) {
            gemm_load_stage(sbase, (c + 1) & 1, Ah, Al, Bh, Bl, m0, n0, (c + 1) * 32, tid);
            CP_COMMIT();
        }
        const uint32_t stg = sbase + (uint32_t)((c & 1) * STG_E) * 2;

#pragma unroll
        for (int ks = 0; ks < 32; ks += 16) {
            uint32_t ah[4][4], bh[8][2];
#pragma unroll
            for (int mt = 0; mt < 4; mt++) {
                const uint32_t ra =
                    (uint32_t)((wm + mt * 16 + a_row) * SPAD + ks + a_colp) * 2;
                LDMAT_X4(ah[mt][0], ah[mt][1], ah[mt][2], ah[mt][3], stg + ra);
            }
#pragma unroll
            for (int np = 0; np < 4; np++) {
                const uint32_t rb =
                    (uint32_t)(EB_H + (wn + np * 16 + b_ntp + b_row) * SPAD + ks + b_colp) * 2;
                LDMAT_X4(bh[np * 2][0], bh[np * 2 + 1][0],
                         bh[np * 2][1], bh[np * 2 + 1][1], stg + rb);
            }
            // hi * hi
#pragma unroll
            for (int mt = 0; mt < 4; mt++)
#pragma unroll
                for (int nt = 0; nt < 8; nt++)
                    mma_bf16(acc[mt][nt], ah[mt][0], ah[mt][1], ah[mt][2], ah[mt][3],
                             bh[nt][0], bh[nt][1]);
            // hi * lo
            {
                uint32_t bl[8][2];
#pragma unroll
                for (int np = 0; np < 4; np++) {
                    const uint32_t rb =
                        (uint32_t)(EB_L + (wn + np * 16 + b_ntp + b_row) * SPAD + ks + b_colp) * 2;
                    LDMAT_X4(bl[np * 2][0], bl[np * 2 + 1][0],
                             bl[np * 2][1], bl[np * 2 + 1][1], stg + rb);
                }
#pragma unroll
                for (int mt = 0; mt < 4; mt++)
#pragma unroll
                    for (int nt = 0; nt < 8; nt++)
                        mma_bf16(acc[mt][nt], ah[mt][0], ah[mt][1], ah[mt][2], ah[mt][3],
                                 bl[nt][0], bl[nt][1]);
            }
            // lo * hi
            {
                uint32_t al[4][4];
#pragma unroll
                for (int mt = 0; mt < 4; mt++) {
                    const uint32_t ra =
                        (uint32_t)(EA_L + (wm + mt * 16 + a_row) * SPAD + ks + a_colp) * 2;
                    LDMAT_X4(al[mt][0], al[mt][1], al[mt][2], al[mt][3], stg + ra);
                }
#pragma unroll
                for (int mt = 0; mt < 4; mt++)
#pragma unroll
                    for (int nt = 0; nt < 8; nt++)
                        mma_bf16(acc[mt][nt], al[mt][0], al[mt][1], al[mt][2], al[mt][3],
                                 bh[nt][0], bh[nt][1]);
            }
        }
    }
    __syncthreads();  // mainloop smem dead; epilogue may reuse it
}

// ===================== fused QKV projection + RoPE + split ===================
// grid (24, 16): blockIdx.x -> {Q: 0-7, K: 8-15, V: 16-23}; 256-col tile = 2 heads.
__global__ __launch_bounds__(256) void qkv_gemm_kernel(const float* __restrict__ cosb,
                                                       const float* __restrict__ sinb) {
    extern __shared__ __nv_bfloat16 dynsm[];
    const uint32_t sbase = smem_u32(dynsm);
    const int tid = threadIdx.x;
    const int wid = tid >> 5, lane = tid & 31;
    const int gg = lane >> 2, tg = lane & 3;
    const int wm = (wid >> 2) * 64, wn = (wid & 3) * 64;
    const int sel = blockIdx.x >> 3;       // 0=Q 1=K 2=V
    const int nblk = blockIdx.x & 7;
    const int n0 = nblk * 256;
    const int m0 = blockIdx.y * 128;

    const int a_row = (lane & 7) + ((lane >> 3) & 1) * 8;
    const int a_colp = (lane >> 4) * 8;
    const int b_row = lane & 7;
    const int b_ntp = ((lane >> 3) & 1) * 8;
    const int b_colp = ((lane >> 4) & 1) * 8;

    const __nv_bfloat16* Bh = (sel == 0) ? g_wqh : (sel == 1) ? g_wkh : g_wvh;
    const __nv_bfloat16* Bl = (sel == 0) ? g_wql : (sel == 1) ? g_wkl : g_wvl;

    float acc[4][8][4];
#pragma unroll
    for (int mt = 0; mt < 4; mt++)
#pragma unroll
        for (int nt = 0; nt < 8; nt++)
#pragma unroll
            for (int j = 0; j < 4; j++) acc[mt][nt][j] = 0.f;

    gemm_mainloop(sbase, g_hh, g_hl, Bh, Bl, m0, n0, tid, wm, wn,
                  a_row, a_colp, b_row, b_ntp, b_colp, acc);

    if (sel == 2) {
        // V: direct register hi/lo split
#pragma unroll
        for (int mt = 0; mt < 4; mt++) {
            const int mA = m0 + wm + mt * 16 + gg;
            const int mB = mA + 8;
#pragma unroll
            for (int nt = 0; nt < 8; nt++) {
                const int n = n0 + wn + nt * 8 + tg * 2;
                const float v0 = acc[mt][nt][0], v1 = acc[mt][nt][1];
                const float v2 = acc[mt][nt][2], v3 = acc[mt][nt][3];
                const float h0 = __bfloat162float(__float2bfloat16(v0));
                const float h1 = __bfloat162float(__float2bfloat16(v1));
                const float h2 = __bfloat162float(__float2bfloat16(v2));
                const float h3 = __bfloat162float(__float2bfloat16(v3));
                *(uint32_t*)&g_vh[(size_t)mA * DM + n] = pack_bf16(v0, v1);
                *(uint32_t*)&g_vl[(size_t)mA * DM + n] = pack_bf16(v0 - h0, v1 - h1);
                *(uint32_t*)&g_vh[(size_t)mB * DM + n] = pack_bf16(v2, v3);
                *(uint32_t*)&g_vl[(size_t)mB * DM + n] = pack_bf16(v2 - h2, v3 - h3);
            }
        }
        return;
    }

    // Q/K: RoPE + hi/lo split in two 128-col passes through reused stage smem
    float* S = (float*)dynsm;
    __nv_bfloat16* Hi = (sel == 0) ? g_qh : g_kh;
    __nv_bfloat16* Lo = (sel == 0) ? g_ql : g_kl;

#pragma unroll 1
    for (int half = 0; half < 2; half++) {
        if (((wid & 3) >> 1) == half) {
            const int wnn = (wid & 1) * 64;  // column position within this half
#pragma unroll
            for (int mt = 0; mt < 4; mt++) {
                const int rA = wm + mt * 16 + gg, rB = rA + 8;
#pragma unroll
                for (int nt = 0; nt < 8; nt++) {
                    const int n = wnn + nt * 8 + tg * 2;
                    S[rA * SROW + n] = acc[mt][nt][0];
                    S[rA * SROW + n + 1] = acc[mt][nt][1];
                    S[rB * SROW + n] = acc[mt][nt][2];
                    S[rB * SROW + n + 1] = acc[mt][nt][3];
                }
            }
        }
        __syncthreads();

        const int head = nblk * 2 + half;
#pragma unroll
        for (int i = 0; i < 8; i++) {
            const int idx = i * 256 + tid;
            const int r = idx >> 4;
            const int c = (idx & 15) * 4;
            const int t = m0 + r;
            float4 x0 = *(const float4*)&S[r * SROW + c];
            float4 x1 = *(const float4*)&S[r * SROW + c + 64];
            float4 c0 = *(const float4*)(cosb + t * DH + c);
            float4 s0 = *(const float4*)(sinb + t * DH + c);
            float4 c1 = *(const float4*)(cosb + t * DH + c + 64);
            float4 s1 = *(const float4*)(sinb + t * DH + c + 64);

            float qa[4], qb[4];
            qa[0] = x0.x * c0.x - x1.x * s0.x; qb[0] = x1.x * c1.x + x0.x * s1.x;
            qa[1] = x0.y * c0.y - x1.y * s0.y; qb[1] = x1.y * c1.y + x0.y * s1.y;
            qa[2] = x0.z * c0.z - x1.z * s0.z; qb[2] = x1.z * c1.z + x0.z * s1.z;
            qa[3] = x0.w * c0.w - x1.w * s0.w; qb[3] = x1.w * c1.w + x0.w * s1.w;

            uint2 hA, lA, hB, lB;
            {
                float ha0 = __bfloat162float(__float2bfloat16(qa[0]));
                float ha1 = __bfloat162float(__float2bfloat16(qa[1]));
                float ha2 = __bfloat162float(__float2bfloat16(qa[2]));
                float ha3 = __bfloat162float(__float2bfloat16(qa[3]));
                hA.x = pack_bf16(qa[0], qa[1]); hA.y = pack_bf16(qa[2], qa[3]);
                lA.x = pack_bf16(qa[0] - ha0, qa[1] - ha1);
                lA.y = pack_bf16(qa[2] - ha2, qa[3] - ha3);
                float hb0 = __bfloat162float(__float2bfloat16(qb[0]));
                float hb1 = __bfloat162float(__float2bfloat16(qb[1]));
                float hb2 = __bfloat162float(__float2bfloat16(qb[2]));
                float hb3 = __bfloat162float(__float2bfloat16(qb[3]));
                hB.x = pack_bf16(qb[0], qb[1]); hB.y = pack_bf16(qb[2], qb[3]);
                lB.x = pack_bf16(qb[0] - hb0, qb[1] - hb1);
                lB.y = pack_bf16(qb[2] - hb2, qb[3] - hb3);
            }
            const size_t base = (size_t)t * DM + head * DH + c;
            *(uint2*)&Hi[base] = hA;      *(uint2*)&Lo[base] = lA;
            *(uint2*)&Hi[base + 64] = hB; *(uint2*)&Lo[base + 64] = lB;
        }
        __syncthreads();
    }
}

// ===================== O projection GEMM (+ residual) ========================
__global__ __launch_bounds__(256) void o_gemm_kernel(float* __restrict__ C,
                                                     const float* __restrict__ R) {
    extern __shared__ __nv_bfloat16 dynsm[];
    const uint32_t sbase = smem_u32(dynsm);
    const int tid = threadIdx.x;
    const int wid = tid >> 5, lane = tid & 31;
    const int gg = lane >> 2, tg = lane & 3;
    const int wm = (wid >> 2) * 64, wn = (wid & 3) * 64;
    const int m0 = blockIdx.y * 128, n0 = blockIdx.x * 256;

    const int a_row = (lane & 7) + ((lane >> 3) & 1) * 8;
    const int a_colp = (lane >> 4) * 8;
    const int b_row = lane & 7;
    const int b_ntp = ((lane >> 3) & 1) * 8;
    const int b_colp = ((lane >> 4) & 1) * 8;

    float acc[4][8][4];
#pragma unroll
    for (int mt = 0; mt < 4; mt++)
#pragma unroll
        for (int nt = 0; nt < 8; nt++)
#pragma unroll
            for (int j = 0; j < 4; j++) acc[mt][nt][j] = 0.f;

    gemm_mainloop(sbase, g_ath, g_atl, g_woh, g_wol, m0, n0, tid, wm, wn,
                  a_row, a_colp, b_row, b_ntp, b_colp, acc);

#pragma unroll
    for (int mt = 0; mt < 4; mt++) {
        const int mA = m0 + wm + mt * 16 + gg;
        const int mB = mA + 8;
#pragma unroll
        for (int nt = 0; nt < 8; nt++) {
            const int n = n0 + wn + nt * 8 + tg * 2;
            float v0 = acc[mt][nt][0], v1 = acc[mt][nt][1];
            float v2 = acc[mt][nt][2], v3 = acc[mt][nt][3];
            float2 r0 = *(const float2*)(R + (size_t)mA * DM + n);
            float2 r1 = *(const float2*)(R + (size_t)mB * DM + n);
            v0 += r0.x; v1 += r0.y; v2 += r1.x; v3 += r1.y;
            *(float2*)(C + (size_t)mA * DM + n) = make_float2(v0, v1);
            *(float2*)(C + (size_t)mB * DM + n) = make_float2(v2, v3);
        }
    }
}

// ===================== flash attention via mma.sync (unchanged) ==============
#define AROW 136
#define ATILE (64 * AROW)
#define ATTN_SMEM (6 * ATILE * 2)  // 104448 bytes

__device__ __forceinline__ void attn_load64(uint32_t sbase, int elem_off,
                                            const __nv_bfloat16* g, int tid) {
#pragma unroll
    for (int t = 0; t < 8; t++) {
        const int idx = t * 128 + tid;
        const int r = idx >> 4, c = idx & 15;
        const uint32_t dst = sbase + (uint32_t)(elem_off + r * AROW + c * 8) * 2;
        CPASYNC16(dst, g + (size_t)r * DM + c * 8);
    }
}

__global__ __launch_bounds__(128) void attn_mma_kernel() {
    extern __shared__ __nv_bfloat16 dynsm[];
    const uint32_t sbase = smem_u32(dynsm);
    const int QH = 0, QL = ATILE, KH = 2 * ATILE, KL = 3 * ATILE,
              VH = 4 * ATILE, VL = 5 * ATILE;
    const int qt = (int)gridDim.x - 1 - (int)blockIdx.x;
    const int h = blockIdx.y;
    const int tid = threadIdx.x, wid = tid >> 5, lane = tid & 31;
    const int gg = lane >> 2, tg = lane & 3;
    const int q0 = qt * 64, wr = wid * 16;
    const float scale = 0.08838834764831845f;

    const int a_row = (lane & 7) + ((lane >> 3) & 1) * 8;
    const int a_colp = (lane >> 4) * 8;
    const int b_row = lane & 7;
    const int b_ntp = ((lane >> 3) & 1) * 8;
    const int b_colp = ((lane >> 4) & 1) * 8;

    attn_load64(sbase, QH, g_qh + (size_t)q0 * DM + h * DH, tid);
    attn_load64(sbase, QL, g_ql + (size_t)q0 * DM + h * DH, tid);
    CP_COMMIT();
    CP_WAIT0();
    __syncthreads();

    float m0 = -1e30f, m1 = -1e30f, l0 = 0.f, l1 = 0.f;
    float o[16][4];
#pragma unroll
    for (int nt = 0; nt < 16; nt++)
#pragma unroll
        for (int j = 0; j < 4; j++) o[nt][j] = 0.f;

    for (int kt = 0; kt <= qt; kt++) {
        const int k0 = kt * 64;
        attn_load64(sbase, KH, g_kh + (size_t)k0 * DM + h * DH, tid);
        attn_load64(sbase, KL, g_kl + (size_t)k0 * DM + h * DH, tid);
        CP_COMMIT();
        attn_load64(sbase, VH, g_vh + (size_t)k0 * DM + h * DH, tid);
        attn_load64(sbase, VL, g_vl + (size_t)k0 * DM + h * DH, tid);
        CP_COMMIT();
        CP_WAIT1();
        __syncthreads();

        float s[8][4];
#pragma unroll
        for (int nt = 0; nt < 8; nt++)
#pragma unroll
            for (int j = 0; j < 4; j++) s[nt][j] = 0.f;

#pragma unroll
        for (int ks = 0; ks < 8; ks++) {
            const int kk = ks * 16;
            uint32_t ah[4], al[4], bh[8][2], bl[8][2];
            const uint32_t ra = (uint32_t)((wr + a_row) * AROW + kk + a_colp) * 2;
            LDMAT_X4(ah[0], ah[1], ah[2], ah[3], sbase + QH * 2 + ra);
            LDMAT_X4(al[0], al[1], al[2], al[3], sbase + QL * 2 + ra);
#pragma unroll
            for (int np = 0; np < 4; np++) {
                const uint32_t rb =
                    (uint32_t)((np * 16 + b_ntp + b_row) * AROW + kk + b_colp) * 2;
                LDMAT_X4(bh[np * 2][0], bh[np * 2 + 1][0],
                         bh[np * 2][1], bh[np * 2 + 1][1], sbase + KH * 2 + rb);
                LDMAT_X4(bl[np * 2][0], bl[np * 2 + 1][0],
                         bl[np * 2][1], bl[np * 2 + 1][1], sbase + KL * 2 + rb);
            }
#pragma unroll
            for (int nt = 0; nt < 8; nt++) {
                mma_bf16(s[nt], ah[0], ah[1], ah[2], ah[3], bh[nt][0], bh[nt][1]);
                mma_bf16(s[nt], ah[0], ah[1], ah[2], ah[3], bl[nt][0], bl[nt][1]);
                mma_bf16(s[nt], al[0], al[1], al[2], al[3], bh[nt][0], bh[nt][1]);
            }
        }

        if (kt == qt) {
            const int r0i = wr + gg, r1i = r0i + 8;
#pragma unroll
            for (int nt = 0; nt < 8; nt++) {
                const int c0 = nt * 8 + tg * 2, c1 = c0 + 1;
                s[nt][0] = (c0 > r0i) ? -1e30f : s[nt][0] * scale;
                s[nt][1] = (c1 > r0i) ? -1e30f : s[nt][1] * scale;
                s[nt][2] = (c0 > r1i) ? -1e30f : s[nt][2] * scale;
                s[nt][3] = (c1 > r1i) ? -1e30f : s[nt][3] * scale;
            }
        } else {
#pragma unroll
            for (int nt = 0; nt < 8; nt++)
#pragma unroll
                for (int j = 0; j < 4; j++) s[nt][j] *= scale;
        }

        float mx0 = -1e30f, mx1 = -1e30f;
#pragma unroll
        for (int nt = 0; nt < 8; nt++) {
            mx0 = fmaxf(mx0, fmaxf(s[nt][0], s[nt][1]));
            mx1 = fmaxf(mx1, fmaxf(s[nt][2], s[nt][3]));
        }
        mx0 = fmaxf(mx0, __shfl_xor_sync(0xffffffffu, mx0, 1));
        mx0 = fmaxf(mx0, __shfl_xor_sync(0xffffffffu, mx0, 2));
        mx1 = fmaxf(mx1, __shfl_xor_sync(0xffffffffu, mx1, 1));
        mx1 = fmaxf(mx1, __shfl_xor_sync(0xffffffffu, mx1, 2));
        const float mn0 = fmaxf(m0, mx0), mn1 = fmaxf(m1, mx1);
        const float a0 = __expf(m0 - mn0), a1 = __expf(m1 - mn1);
        m0 = mn0; m1 = mn1;
        float rs0 = 0.f, rs1 = 0.f;
#pragma unroll
        for (int nt = 0; nt < 8; nt++) {
            s[nt][0] = __expf(s[nt][0] - mn0); rs0 += s[nt][0];
            s[nt][1] = __expf(s[nt][1] - mn0); rs0 += s[nt][1];
            s[nt][2] = __expf(s[nt][2] - mn1); rs1 += s[nt][2];
            s[nt][3] = __expf(s[nt][3] - mn1); rs1 += s[nt][3];
        }
        rs0 += __shfl_xor_sync(0xffffffffu, rs0, 1);
        rs0 += __shfl_xor_sync(0xffffffffu, rs0, 2);
        rs1 += __shfl_xor_sync(0xffffffffu, rs1, 1);
        rs1 += __shfl_xor_sync(0xffffffffu, rs1, 2);
        l0 = l0 * a0 + rs0;
        l1 = l1 * a1 + rs1;
#pragma unroll
        for (int nt = 0; nt < 16; nt++) {
            o[nt][0] *= a0; o[nt][1] *= a0;
            o[nt][2] *= a1; o[nt][3] *= a1;
        }

        CP_WAIT0();
        __syncthreads();

#pragma unroll
        for (int kp = 0; kp < 4; kp++) {
            const int j0 = kp * 2, j1 = j0 + 1;
            const float v00 = s[j0][0], v01 = s[j0][1], v02 = s[j0][2], v03 = s[j0][3];
            const float v10 = s[j1][0], v11 = s[j1][1], v12 = s[j1][2], v13 = s[j1][3];
            const float h00 = __bfloat162float(__float2bfloat16(v00));
            const float h01 = __bfloat162float(__float2bfloat16(v01));
            const float h02 = __bfloat162float(__float2bfloat16(v02));
            const float h03 = __bfloat162float(__float2bfloat16(v03));
            const float h10 = __bfloat162float(__float2bfloat16(v10));
            const float h11 = __bfloat162float(__float2bfloat16(v11));
            const float h12 = __bfloat162float(__float2bfloat16(v12));
            const float h13 = __bfloat162float(__float2bfloat16(v13));
            const uint32_t ph0 = pack_bf16(v00, v01), ph1 = pack_bf16(v02, v03);
            const uint32_t ph2 = pack_bf16(v10, v11), ph3 = pack_bf16(v12, v13);
            const uint32_t pl0 = pack_bf16(v00 - h00, v01 - h01);
            const uint32_t pl1 = pack_bf16(v02 - h02, v03 - h03);
            const uint32_t pl2 = pack_bf16(v10 - h10, v11 - h11);
            const uint32_t pl3 = pack_bf16(v12 - h12, v13 - h13);

            const uint32_t vrow_h =
                sbase + (uint32_t)(VH + (kp * 16 + (lane & 15)) * AROW) * 2;
            const uint32_t vrow_l =
                sbase + (uint32_t)(VL + (kp * 16 + (lane & 15)) * AROW) * 2;
#pragma unroll
            for (int nt = 0; nt < 16; nt++) {
                uint32_t bh0, bh1, bl0, bl1;
                LDMAT_X2_T(bh0, bh1, vrow_h + nt * 16);
                LDMAT_X2_T(bl0, bl1, vrow_l + nt * 16);
                mma_bf16(o[nt], ph0, ph1, ph2, ph3, bh0, bh1);
                mma_bf16(o[nt], ph0, ph1, ph2, ph3, bl0, bl1);
                mma_bf16(o[nt], pl0, pl1, pl2, pl3, bh0, bh1);
            }
        }
        __syncthreads();
    }

    const float inv0 = 1.f / l0, inv1 = 1.f / l1;
    const int r0 = q0 + wr + gg, r1 = r0 + 8;
    const int colb = h * DH + tg * 2;
#pragma unroll
    for (int nt = 0; nt < 16; nt++) {
        const int col = colb + nt * 8;
        const float f0 = o[nt][0] * inv0, f1 = o[nt][1] * inv0;
        const float f2 = o[nt][2] * inv1, f3 = o[nt][3] * inv1;
        const float h0 = __bfloat162float(__float2bfloat16(f0));
        const float h1 = __bfloat162float(__float2bfloat16(f1));
        const float h2 = __bfloat162float(__float2bfloat16(f2));
        const float h3 = __bfloat162float(__float2bfloat16(f3));
        *(uint32_t*)&g_ath[(size_t)r0 * DM + col] = pack_bf16(f0, f1);
        *(uint32_t*)&g_atl[(size_t)r0 * DM + col] = pack_bf16(f0 - h0, f1 - h1);
        *(uint32_t*)&g_ath[(size_t)r1 * DM + col] = pack_bf16(f2, f3);
        *(uint32_t*)&g_atl[(size_t)r1 * DM + col] = pack_bf16(f2 - h2, f3 - h3);
    }
}

// ===================== launcher ==============================================
extern "C" void kernel_launch(void* const* d_in, const int* in_sizes, int n_in,
                              void* d_out, int out_size) {
    const float* x    = (const float*)d_in[0];
    const float* w_ln = (const float*)d_in[1];
    const float* wq   = (const float*)d_in[2];
    const float* wk   = (const float*)d_in[3];
    const float* wv   = (const float*)d_in[4];
    const float* wo   = (const float*)d_in[5];
    const float* cosb = (const float*)d_in[6];
    const float* sinb = (const float*)d_in[7];
    float* out = (float*)d_out;

    (void)cudaFuncSetAttribute(qkv_gemm_kernel,
                               cudaFuncAttributeMaxDynamicSharedMemorySize, GEMM_SMEM);
    (void)cudaFuncSetAttribute(o_gemm_kernel,
                               cudaFuncAttributeMaxDynamicSharedMemorySize, GEMM_SMEM);
    (void)cudaFuncSetAttribute(attn_mma_kernel,
                               cudaFuncAttributeMaxDynamicSharedMemorySize, ATTN_SMEM);

    split_all_kernel<<<4 * 4096, 256>>>(wq, wk, wv, wo);
    rmsnorm_kernel<<<TT, 256>>>(x, w_ln);
    qkv_gemm_kernel<<<dim3(24, 16), 256, GEMM_SMEM>>>(cosb, sinb);
    attn_mma_kernel<<<dim3(TT / 64, NH), 128, ATTN_SMEM>>>();
    o_gemm_kernel<<<dim3(8, 16), 256, GEMM_SMEM>>>(out, x);
}

// round 12
// speedup vs baseline: 1.0038x; 1.0038x over previous
#include <cuda_runtime.h>
#include <cuda_bf16.h>
#include <cstdint>
#include <math.h>

#define TT 2048
#define DM 2048
#define NH 16
#define DH 128

// ===================== PTX helpers ==========================================
__device__ __forceinline__ uint32_t smem_u32(const void* p) {
    uint32_t a;
    asm("{ .reg .u64 t; cvta.to.shared.u64 t, %1; cvt.u32.u64 %0, t; }"
        : "=r"(a) : "l"(p));
    return a;
}

#define CPASYNC16(dst, src) \
    asm volatile("cp.async.cg.shared.global [%0], [%1], 16;" :: "r"(dst), "l"(src))
#define CP_COMMIT() asm volatile("cp.async.commit_group;" ::: "memory")
#define CP_WAIT0() asm volatile("cp.async.wait_group 0;" ::: "memory")
#define CP_WAIT1() asm volatile("cp.async.wait_group 1;" ::: "memory")

#define LDMAT_X4(r0, r1, r2, r3, addr) \
    asm volatile("ldmatrix.sync.aligned.m8n8.x4.shared.b16 {%0,%1,%2,%3}, [%4];" \
                 : "=r"(r0), "=r"(r1), "=r"(r2), "=r"(r3) : "r"(addr))
#define LDMAT_X2_T(b0, b1, addr) \
    asm volatile("ldmatrix.sync.aligned.m8n8.x2.trans.shared.b16 {%0,%1}, [%2];" \
                 : "=r"(b0), "=r"(b1) : "r"(addr))

__device__ __forceinline__ void mma_bf16(float* c, uint32_t a0, uint32_t a1,
                                         uint32_t a2, uint32_t a3,
                                         uint32_t b0, uint32_t b1) {
    asm volatile(
        "mma.sync.aligned.m16n8k16.row.col.f32.bf16.bf16.f32 "
        "{%0,%1,%2,%3}, {%4,%5,%6,%7}, {%8,%9}, {%0,%1,%2,%3};"
        : "+f"(c[0]), "+f"(c[1]), "+f"(c[2]), "+f"(c[3])
        : "r"(a0), "r"(a1), "r"(a2), "r"(a3), "r"(b0), "r"(b1));
}

__device__ __forceinline__ uint32_t pack_bf16(float a, float b) {
    __nv_bfloat162 t = __floats2bfloat162_rn(a, b);
    return *(uint32_t*)&t;
}

// ===================== scratch (static device globals) =======================
__device__ __nv_bfloat16 g_hh[(size_t)TT * DM], g_hl[(size_t)TT * DM];
__device__ __nv_bfloat16 g_ath[(size_t)TT * DM], g_atl[(size_t)TT * DM];
__device__ __nv_bfloat16 g_qh[(size_t)TT * DM], g_ql[(size_t)TT * DM];
__device__ __nv_bfloat16 g_kh[(size_t)TT * DM], g_kl[(size_t)TT * DM];
__device__ __nv_bfloat16 g_vh[(size_t)TT * DM], g_vl[(size_t)TT * DM];
__device__ __nv_bfloat16 g_wqh[(size_t)DM * DM], g_wql[(size_t)DM * DM];
__device__ __nv_bfloat16 g_wkh[(size_t)DM * DM], g_wkl[(size_t)DM * DM];
__device__ __nv_bfloat16 g_wvh[(size_t)DM * DM], g_wvl[(size_t)DM * DM];
__device__ __nv_bfloat16 g_woh[(size_t)DM * DM], g_wol[(size_t)DM * DM];

// ===================== fused split of all 4 weights ==========================
__global__ __launch_bounds__(256) void split_all_kernel(
    const float* __restrict__ wq, const float* __restrict__ wk,
    const float* __restrict__ wv, const float* __restrict__ wo) {
    const int w = blockIdx.x >> 12;
    const int blk = blockIdx.x & 4095;
    const float* X = (w == 0) ? wq : (w == 1) ? wk : (w == 2) ? wv : wo;
    __nv_bfloat16* Hi = (w == 0) ? g_wqh : (w == 1) ? g_wkh : (w == 2) ? g_wvh : g_woh;
    __nv_bfloat16* Lo = (w == 0) ? g_wql : (w == 1) ? g_wkl : (w == 2) ? g_wvl : g_wol;

    const int i = (blk * 256 + threadIdx.x) * 4;
    float4 v = *(const float4*)(X + i);
    float f[4] = {v.x, v.y, v.z, v.w};
    unsigned short hb[4], lb[4];
#pragma unroll
    for (int j = 0; j < 4; j++) {
        __nv_bfloat16 h = __float2bfloat16(f[j]);
        __nv_bfloat16 l = __float2bfloat16(f[j] - __bfloat162float(h));
        hb[j] = __bfloat16_as_ushort(h);
        lb[j] = __bfloat16_as_ushort(l);
    }
    uint2 hv, lv;
    hv.x = (uint32_t)hb[0] | ((uint32_t)hb[1] << 16);
    hv.y = (uint32_t)hb[2] | ((uint32_t)hb[3] << 16);
    lv.x = (uint32_t)lb[0] | ((uint32_t)lb[1] << 16);
    lv.y = (uint32_t)lb[2] | ((uint32_t)lb[3] << 16);
    *(uint2*)(Hi + i) = hv;
    *(uint2*)(Lo + i) = lv;
}

// ===================== RMSNorm (emits bf16 hi/lo) ============================
__global__ __launch_bounds__(256) void rmsnorm_kernel(const float* __restrict__ x,
                                                      const float* __restrict__ w) {
    __shared__ float red[256];
    const int row = blockIdx.x;
    const int tid = threadIdx.x;
    const float* xr = x + (size_t)row * DM;
    float s = 0.f;
    for (int i = tid; i < DM; i += 256) { float v = xr[i]; s += v * v; }
    red[tid] = s;
    __syncthreads();
    for (int o = 128; o > 0; o >>= 1) {
        if (tid < o) red[tid] += red[tid + o];
        __syncthreads();
    }
    const float inv = rsqrtf(red[0] / (float)DM + 1e-5f);
    __nv_bfloat16* hh = g_hh + (size_t)row * DM;
    __nv_bfloat16* hl = g_hl + (size_t)row * DM;
    for (int i = tid; i < DM; i += 256) {
        float y = w[i] * xr[i] * inv;
        __nv_bfloat16 h = __float2bfloat16(y);
        hh[i] = h;
        hl[i] = __float2bfloat16(y - __bfloat162float(h));
    }
}

// ===================== shared GEMM machinery =================================
// CTA tile 128(M) x 256(N), BK=32, 8 warps in 2(M)x4(N) -> warp tile 64x64.
#define SPAD 40
#define EA_L (128 * SPAD)        // elem offsets inside a stage
#define EB_H (256 * SPAD)
#define EB_L (512 * SPAD)
#define STG_E (768 * SPAD)       // stage elems
#define GEMM_SMEM (2 * STG_E * 2)  // 122880 bytes
#define SROW 132                 // fp32 epilogue staging row stride

__device__ __forceinline__ void gemm_load_stage(
    uint32_t sbase, int st,
    const __nv_bfloat16* Ah, const __nv_bfloat16* Al,
    const __nv_bfloat16* Bh, const __nv_bfloat16* Bl,
    int m0, int n0, int k0, int tid) {
    const uint32_t sb = sbase + (uint32_t)(st * STG_E) * 2;
    const __nv_bfloat16* pAh = Ah + (size_t)m0 * DM + k0;
    const __nv_bfloat16* pAl = Al + (size_t)m0 * DM + k0;
    const __nv_bfloat16* pBh = Bh + (size_t)n0 * DM + k0;
    const __nv_bfloat16* pBl = Bl + (size_t)n0 * DM + k0;
#pragma unroll
    for (int i = 0; i < 2; i++) {
        const int idx = i * 256 + tid;
        const int r = idx >> 2, c = idx & 3;
        CPASYNC16(sb + (uint32_t)(r * SPAD + c * 8) * 2, pAh + (size_t)r * DM + c * 8);
        CPASYNC16(sb + (uint32_t)(EA_L + r * SPAD + c * 8) * 2, pAl + (size_t)r * DM + c * 8);
    }
#pragma unroll
    for (int i = 0; i < 4; i++) {
        const int idx = i * 256 + tid;
        const int r = idx >> 2, c = idx & 3;
        CPASYNC16(sb + (uint32_t)(EB_H + r * SPAD + c * 8) * 2, pBh + (size_t)r * DM + c * 8);
        CPASYNC16(sb + (uint32_t)(EB_L + r * SPAD + c * 8) * 2, pBl + (size_t)r * DM + c * 8);
    }
}

__device__ __forceinline__ void gemm_mainloop(
    uint32_t sbase, const __nv_bfloat16* Ah, const __nv_bfloat16* Al,
    const __nv_bfloat16* Bh, const __nv_bfloat16* Bl,
    int m0, int n0, int tid, int wm, int wn,
    int a_row, int a_colp, int b_row, int b_ntp, int b_colp,
    float acc[4][8][4]) {
    gemm_load_stage(sbase, 0, Ah, Al, Bh, Bl, m0, n0, 0, tid);
    CP_COMMIT();

    for (int c = 0; c < DM / 32; c++) {
        CP_WAIT0();
        __syncthreads();
        if (c + 1 < DM / 32) {
            gemm_load_stage(sbase, (c + 1) & 1, Ah, Al, Bh, Bl, m0, n0, (c + 1) * 32, tid);
            CP_COMMIT();
        }
        const uint32_t stg = sbase + (uint32_t)((c & 1) * STG_E) * 2;

#pragma unroll
        for (int ks = 0; ks < 32; ks += 16) {
            uint32_t ah[4][4], bh[8][2];
#pragma unroll
            for (int mt = 0; mt < 4; mt++) {
                const uint32_t ra =
                    (uint32_t)((wm + mt * 16 + a_row) * SPAD + ks + a_colp) * 2;
                LDMAT_X4(ah[mt][0], ah[mt][1], ah[mt][2], ah[mt][3], stg + ra);
            }
#pragma unroll
            for (int np = 0; np < 4; np++) {
                const uint32_t rb =
                    (uint32_t)(EB_H + (wn + np * 16 + b_ntp + b_row) * SPAD + ks + b_colp) * 2;
                LDMAT_X4(bh[np * 2][0], bh[np * 2 + 1][0],
                         bh[np * 2][1], bh[np * 2 + 1][1], stg + rb);
            }
#pragma unroll
            for (int mt = 0; mt < 4; mt++)
#pragma unroll
                for (int nt = 0; nt < 8; nt++)
                    mma_bf16(acc[mt][nt], ah[mt][0], ah[mt][1], ah[mt][2], ah[mt][3],
                             bh[nt][0], bh[nt][1]);
            {
                uint32_t bl[8][2];
#pragma unroll
                for (int np = 0; np < 4; np++) {
                    const uint32_t rb =
                        (uint32_t)(EB_L + (wn + np * 16 + b_ntp + b_row) * SPAD + ks + b_colp) * 2;
                    LDMAT_X4(bl[np * 2][0], bl[np * 2 + 1][0],
                             bl[np * 2][1], bl[np * 2 + 1][1], stg + rb);
                }
#pragma unroll
                for (int mt = 0; mt < 4; mt++)
#pragma unroll
                    for (int nt = 0; nt < 8; nt++)
                        mma_bf16(acc[mt][nt], ah[mt][0], ah[mt][1], ah[mt][2], ah[mt][3],
                                 bl[nt][0], bl[nt][1]);
            }
            {
                uint32_t al[4][4];
#pragma unroll
                for (int mt = 0; mt < 4; mt++) {
                    const uint32_t ra =
                        (uint32_t)(EA_L + (wm + mt * 16 + a_row) * SPAD + ks + a_colp) * 2;
                    LDMAT_X4(al[mt][0], al[mt][1], al[mt][2], al[mt][3], stg + ra);
                }
#pragma unroll
                for (int mt = 0; mt < 4; mt++)
#pragma unroll
                    for (int nt = 0; nt < 8; nt++)
                        mma_bf16(acc[mt][nt], al[mt][0], al[mt][1], al[mt][2], al[mt][3],
                                 bh[nt][0], bh[nt][1]);
            }
        }
    }
    __syncthreads();  // mainloop smem dead; epilogue may reuse it
}

// ===================== fused QKV projection + RoPE + split ===================
// grid (24, 16): blockIdx.x -> {Q: 0-7, K: 8-15, V: 16-23}; 256-col tile = 2 heads.
__global__ __launch_bounds__(256) void qkv_gemm_kernel(const float* __restrict__ cosb,
                                                       const float* __restrict__ sinb) {
    extern __shared__ __nv_bfloat16 dynsm[];
    const uint32_t sbase = smem_u32(dynsm);
    const int tid = threadIdx.x;
    const int wid = tid >> 5, lane = tid & 31;
    const int gg = lane >> 2, tg = lane & 3;
    const int wm = (wid >> 2) * 64, wn = (wid & 3) * 64;
    const int sel = blockIdx.x >> 3;       // 0=Q 1=K 2=V
    const int nblk = blockIdx.x & 7;
    const int n0 = nblk * 256;
    const int m0 = blockIdx.y * 128;

    const int a_row = (lane & 7) + ((lane >> 3) & 1) * 8;
    const int a_colp = (lane >> 4) * 8;
    const int b_row = lane & 7;
    const int b_ntp = ((lane >> 3) & 1) * 8;
    const int b_colp = ((lane >> 4) & 1) * 8;

    const __nv_bfloat16* Bh = (sel == 0) ? g_wqh : (sel == 1) ? g_wkh : g_wvh;
    const __nv_bfloat16* Bl = (sel == 0) ? g_wql : (sel == 1) ? g_wkl : g_wvl;

    float acc[4][8][4];
#pragma unroll
    for (int mt = 0; mt < 4; mt++)
#pragma unroll
        for (int nt = 0; nt < 8; nt++)
#pragma unroll
            for (int j = 0; j < 4; j++) acc[mt][nt][j] = 0.f;

    gemm_mainloop(sbase, g_hh, g_hl, Bh, Bl, m0, n0, tid, wm, wn,
                  a_row, a_colp, b_row, b_ntp, b_colp, acc);

    if (sel == 2) {
#pragma unroll
        for (int mt = 0; mt < 4; mt++) {
            const int mA = m0 + wm + mt * 16 + gg;
            const int mB = mA + 8;
#pragma unroll
            for (int nt = 0; nt < 8; nt++) {
                const int n = n0 + wn + nt * 8 + tg * 2;
                const float v0 = acc[mt][nt][0], v1 = acc[mt][nt][1];
                const float v2 = acc[mt][nt][2], v3 = acc[mt][nt][3];
                const float h0 = __bfloat162float(__float2bfloat16(v0));
                const float h1 = __bfloat162float(__float2bfloat16(v1));
                const float h2 = __bfloat162float(__float2bfloat16(v2));
                const float h3 = __bfloat162float(__float2bfloat16(v3));
                *(uint32_t*)&g_vh[(size_t)mA * DM + n] = pack_bf16(v0, v1);
                *(uint32_t*)&g_vl[(size_t)mA * DM + n] = pack_bf16(v0 - h0, v1 - h1);
                *(uint32_t*)&g_vh[(size_t)mB * DM + n] = pack_bf16(v2, v3);
                *(uint32_t*)&g_vl[(size_t)mB * DM + n] = pack_bf16(v2 - h2, v3 - h3);
            }
        }
        return;
    }

    // Q/K: RoPE + hi/lo split in two 128-col passes through reused stage smem
    float* S = (float*)dynsm;
    __nv_bfloat16* Hi = (sel == 0) ? g_qh : g_kh;
    __nv_bfloat16* Lo = (sel == 0) ? g_ql : g_kl;

#pragma unroll 1
    for (int half = 0; half < 2; half++) {
        if (((wid & 3) >> 1) == half) {
            const int wnn = (wid & 1) * 64;
#pragma unroll
            for (int mt = 0; mt < 4; mt++) {
                const int rA = wm + mt * 16 + gg, rB = rA + 8;
#pragma unroll
                for (int nt = 0; nt < 8; nt++) {
                    const int n = wnn + nt * 8 + tg * 2;
                    S[rA * SROW + n] = acc[mt][nt][0];
                    S[rA * SROW + n + 1] = acc[mt][nt][1];
                    S[rB * SROW + n] = acc[mt][nt][2];
                    S[rB * SROW + n + 1] = acc[mt][nt][3];
                }
            }
        }
        __syncthreads();

        const int head = nblk * 2 + half;
#pragma unroll
        for (int i = 0; i < 8; i++) {
            const int idx = i * 256 + tid;
            const int r = idx >> 4;
            const int c = (idx & 15) * 4;
            const int t = m0 + r;
            float4 x0 = *(const float4*)&S[r * SROW + c];
            float4 x1 = *(const float4*)&S[r * SROW + c + 64];
            float4 c0 = *(const float4*)(cosb + t * DH + c);
            float4 s0 = *(const float4*)(sinb + t * DH + c);
            float4 c1 = *(const float4*)(cosb + t * DH + c + 64);
            float4 s1 = *(const float4*)(sinb + t * DH + c + 64);

            float qa[4], qb[4];
            qa[0] = x0.x * c0.x - x1.x * s0.x; qb[0] = x1.x * c1.x + x0.x * s1.x;
            qa[1] = x0.y * c0.y - x1.y * s0.y; qb[1] = x1.y * c1.y + x0.y * s1.y;
            qa[2] = x0.z * c0.z - x1.z * s0.z; qb[2] = x1.z * c1.z + x0.z * s1.z;
            qa[3] = x0.w * c0.w - x1.w * s0.w; qb[3] = x1.w * c1.w + x0.w * s1.w;

            uint2 hA, lA, hB, lB;
            {
                float ha0 = __bfloat162float(__float2bfloat16(qa[0]));
                float ha1 = __bfloat162float(__float2bfloat16(qa[1]));
                float ha2 = __bfloat162float(__float2bfloat16(qa[2]));
                float ha3 = __bfloat162float(__float2bfloat16(qa[3]));
                hA.x = pack_bf16(qa[0], qa[1]); hA.y = pack_bf16(qa[2], qa[3]);
                lA.x = pack_bf16(qa[0] - ha0, qa[1] - ha1);
                lA.y = pack_bf16(qa[2] - ha2, qa[3] - ha3);
                float hb0 = __bfloat162float(__float2bfloat16(qb[0]));
                float hb1 = __bfloat162float(__float2bfloat16(qb[1]));
                float hb2 = __bfloat162float(__float2bfloat16(qb[2]));
                float hb3 = __bfloat162float(__float2bfloat16(qb[3]));
                hB.x = pack_bf16(qb[0], qb[1]); hB.y = pack_bf16(qb[2], qb[3]);
                lB.x = pack_bf16(qb[0] - hb0, qb[1] - hb1);
                lB.y = pack_bf16(qb[2] - hb2, qb[3] - hb3);
            }
            const size_t base = (size_t)t * DM + head * DH + c;
            *(uint2*)&Hi[base] = hA;      *(uint2*)&Lo[base] = lA;
            *(uint2*)&Hi[base + 64] = hB; *(uint2*)&Lo[base + 64] = lB;
        }
        __syncthreads();
    }
}

// ===================== O projection GEMM (+ residual) ========================
__global__ __launch_bounds__(256) void o_gemm_kernel(float* __restrict__ C,
                                                     const float* __restrict__ R) {
    extern __shared__ __nv_bfloat16 dynsm[];
    const uint32_t sbase = smem_u32(dynsm);
    const int tid = threadIdx.x;
    const int wid = tid >> 5, lane = tid & 31;
    const int gg = lane >> 2, tg = lane & 3;
    const int wm = (wid >> 2) * 64, wn = (wid & 3) * 64;
    const int m0 = blockIdx.y * 128, n0 = blockIdx.x * 256;

    const int a_row = (lane & 7) + ((lane >> 3) & 1) * 8;
    const int a_colp = (lane >> 4) * 8;
    const int b_row = lane & 7;
    const int b_ntp = ((lane >> 3) & 1) * 8;
    const int b_colp = ((lane >> 4) & 1) * 8;

    float acc[4][8][4];
#pragma unroll
    for (int mt = 0; mt < 4; mt++)
#pragma unroll
        for (int nt = 0; nt < 8; nt++)
#pragma unroll
            for (int j = 0; j < 4; j++) acc[mt][nt][j] = 0.f;

    gemm_mainloop(sbase, g_ath, g_atl, g_woh, g_wol, m0, n0, tid, wm, wn,
                  a_row, a_colp, b_row, b_ntp, b_colp, acc);

#pragma unroll
    for (int mt = 0; mt < 4; mt++) {
        const int mA = m0 + wm + mt * 16 + gg;
        const int mB = mA + 8;
#pragma unroll
        for (int nt = 0; nt < 8; nt++) {
            const int n = n0 + wn + nt * 8 + tg * 2;
            float v0 = acc[mt][nt][0], v1 = acc[mt][nt][1];
            float v2 = acc[mt][nt][2], v3 = acc[mt][nt][3];
            float2 r0 = *(const float2*)(R + (size_t)mA * DM + n);
            float2 r1 = *(const float2*)(R + (size_t)mB * DM + n);
            v0 += r0.x; v1 += r0.y; v2 += r1.x; v3 += r1.y;
            *(float2*)(C + (size_t)mA * DM + n) = make_float2(v0, v1);
            *(float2*)(C + (size_t)mB * DM + n) = make_float2(v2, v3);
        }
    }
}

// ===================== flash attention: deferred single-buffer prefetch ======
#define AROW 136
#define ATILE (64 * AROW)
#define ATTN_SMEM (6 * ATILE * 2)  // 104448 bytes -> 2 CTAs/SM

__device__ __forceinline__ void attn_load64(uint32_t sbase, int elem_off,
                                            const __nv_bfloat16* g, int tid) {
#pragma unroll
    for (int t = 0; t < 8; t++) {
        const int idx = t * 128 + tid;
        const int r = idx >> 4, c = idx & 15;
        const uint32_t dst = sbase + (uint32_t)(elem_off + r * AROW + c * 8) * 2;
        CPASYNC16(dst, g + (size_t)r * DM + c * 8);
    }
}

__global__ __launch_bounds__(128) void attn_mma_kernel() {
    extern __shared__ __nv_bfloat16 dynsm[];
    const uint32_t sbase = smem_u32(dynsm);
    const int QH = 0, QL = ATILE, KH = 2 * ATILE, KL = 3 * ATILE,
              VH = 4 * ATILE, VL = 5 * ATILE;
    const int qt = (int)gridDim.x - 1 - (int)blockIdx.x;  // long tiles first
    const int h = blockIdx.y;
    const int tid = threadIdx.x, wid = tid >> 5, lane = tid & 31;
    const int gg = lane >> 2, tg = lane & 3;
    const int q0 = qt * 64, wr = wid * 16;
    const float scale = 0.08838834764831845f;

    const int a_row = (lane & 7) + ((lane >> 3) & 1) * 8;
    const int a_colp = (lane >> 4) * 8;
    const int b_row = lane & 7;
    const int b_ntp = ((lane >> 3) & 1) * 8;
    const int b_colp = ((lane >> 4) & 1) * 8;

    // prologue: Q tiles, then K(0)+V(0) prefetch
    attn_load64(sbase, QH, g_qh + (size_t)q0 * DM + h * DH, tid);
    attn_load64(sbase, QL, g_ql + (size_t)q0 * DM + h * DH, tid);
    CP_COMMIT();
    CP_WAIT0();
    __syncthreads();
    attn_load64(sbase, KH, g_kh + (size_t)0 + h * DH, tid);
    attn_load64(sbase, KL, g_kl + (size_t)0 + h * DH, tid);
    CP_COMMIT();
    attn_load64(sbase, VH, g_vh + (size_t)0 + h * DH, tid);
    attn_load64(sbase, VL, g_vl + (size_t)0 + h * DH, tid);
    CP_COMMIT();

    float m0 = -1e30f, m1 = -1e30f, l0 = 0.f, l1 = 0.f;
    float o[16][4];
#pragma unroll
    for (int nt = 0; nt < 16; nt++)
#pragma unroll
        for (int j = 0; j < 4; j++) o[nt][j] = 0.f;

    for (int kt = 0; kt <= qt; kt++) {
        // wait K(kt): pending groups = {K(kt), V(kt)}
        CP_WAIT1();
        __syncthreads();

        // ---- S = Q K^T (split 3-product) ----
        float s[8][4];
#pragma unroll
        for (int nt = 0; nt < 8; nt++)
#pragma unroll
            for (int j = 0; j < 4; j++) s[nt][j] = 0.f;

#pragma unroll
        for (int ks = 0; ks < 8; ks++) {
            const int kk = ks * 16;
            uint32_t ah[4], al[4], bh[8][2], bl[8][2];
            const uint32_t ra = (uint32_t)((wr + a_row) * AROW + kk + a_colp) * 2;
            LDMAT_X4(ah[0], ah[1], ah[2], ah[3], sbase + QH * 2 + ra);
            LDMAT_X4(al[0], al[1], al[2], al[3], sbase + QL * 2 + ra);
#pragma unroll
            for (int np = 0; np < 4; np++) {
                const uint32_t rb =
                    (uint32_t)((np * 16 + b_ntp + b_row) * AROW + kk + b_colp) * 2;
                LDMAT_X4(bh[np * 2][0], bh[np * 2 + 1][0],
                         bh[np * 2][1], bh[np * 2 + 1][1], sbase + KH * 2 + rb);
                LDMAT_X4(bl[np * 2][0], bl[np * 2 + 1][0],
                         bl[np * 2][1], bl[np * 2 + 1][1], sbase + KL * 2 + rb);
            }
#pragma unroll
            for (int nt = 0; nt < 8; nt++) {
                mma_bf16(s[nt], ah[0], ah[1], ah[2], ah[3], bh[nt][0], bh[nt][1]);
                mma_bf16(s[nt], ah[0], ah[1], ah[2], ah[3], bl[nt][0], bl[nt][1]);
                mma_bf16(s[nt], al[0], al[1], al[2], al[3], bh[nt][0], bh[nt][1]);
            }
        }

        // K buffers consumed -> prefetch K(kt+1) (hidden behind softmax + PV)
        __syncthreads();
        if (kt < qt) {
            const int kn = (kt + 1) * 64;
            attn_load64(sbase, KH, g_kh + (size_t)kn * DM + h * DH, tid);
            attn_load64(sbase, KL, g_kl + (size_t)kn * DM + h * DH, tid);
            CP_COMMIT();
        }

        // ---- scale + causal mask ----
        if (kt == qt) {
            const int r0i = wr + gg, r1i = r0i + 8;
#pragma unroll
            for (int nt = 0; nt < 8; nt++) {
                const int c0 = nt * 8 + tg * 2, c1 = c0 + 1;
                s[nt][0] = (c0 > r0i) ? -1e30f : s[nt][0] * scale;
                s[nt][1] = (c1 > r0i) ? -1e30f : s[nt][1] * scale;
                s[nt][2] = (c0 > r1i) ? -1e30f : s[nt][2] * scale;
                s[nt][3] = (c1 > r1i) ? -1e30f : s[nt][3] * scale;
            }
        } else {
#pragma unroll
            for (int nt = 0; nt < 8; nt++)
#pragma unroll
                for (int j = 0; j < 4; j++) s[nt][j] *= scale;
        }

        // ---- online softmax ----
        float mx0 = -1e30f, mx1 = -1e30f;
#pragma unroll
        for (int nt = 0; nt < 8; nt++) {
            mx0 = fmaxf(mx0, fmaxf(s[nt][0], s[nt][1]));
            mx1 = fmaxf(mx1, fmaxf(s[nt][2], s[nt][3]));
        }
        mx0 = fmaxf(mx0, __shfl_xor_sync(0xffffffffu, mx0, 1));
        mx0 = fmaxf(mx0, __shfl_xor_sync(0xffffffffu, mx0, 2));
        mx1 = fmaxf(mx1, __shfl_xor_sync(0xffffffffu, mx1, 1));
        mx1 = fmaxf(mx1, __shfl_xor_sync(0xffffffffu, mx1, 2));
        const float mn0 = fmaxf(m0, mx0), mn1 = fmaxf(m1, mx1);
        const float a0 = __expf(m0 - mn0), a1 = __expf(m1 - mn1);
        m0 = mn0; m1 = mn1;
        float rs0 = 0.f, rs1 = 0.f;
#pragma unroll
        for (int nt = 0; nt < 8; nt++) {
            s[nt][0] = __expf(s[nt][0] - mn0); rs0 += s[nt][0];
            s[nt][1] = __expf(s[nt][1] - mn0); rs0 += s[nt][1];
            s[nt][2] = __expf(s[nt][2] - mn1); rs1 += s[nt][2];
            s[nt][3] = __expf(s[nt][3] - mn1); rs1 += s[nt][3];
        }
        rs0 += __shfl_xor_sync(0xffffffffu, rs0, 1);
        rs0 += __shfl_xor_sync(0xffffffffu, rs0, 2);
        rs1 += __shfl_xor_sync(0xffffffffu, rs1, 1);
        rs1 += __shfl_xor_sync(0xffffffffu, rs1, 2);
        l0 = l0 * a0 + rs0;
        l1 = l1 * a1 + rs1;
#pragma unroll
        for (int nt = 0; nt < 16; nt++) {
            o[nt][0] *= a0; o[nt][1] *= a0;
            o[nt][2] *= a1; o[nt][3] *= a1;
        }

        // wait V(kt): pending = {V(kt)} (+ K(kt+1) if committed)
        if (kt < qt) CP_WAIT1(); else CP_WAIT0();
        __syncthreads();

        // ---- O += P V (split 3-product; V^T via ldmatrix.trans) ----
#pragma unroll
        for (int kp = 0; kp < 4; kp++) {
            const int j0 = kp * 2, j1 = j0 + 1;
            const float v00 = s[j0][0], v01 = s[j0][1], v02 = s[j0][2], v03 = s[j0][3];
            const float v10 = s[j1][0], v11 = s[j1][1], v12 = s[j1][2], v13 = s[j1][3];
            const float h00 = __bfloat162float(__float2bfloat16(v00));
            const float h01 = __bfloat162float(__float2bfloat16(v01));
            const float h02 = __bfloat162float(__float2bfloat16(v02));
            const float h03 = __bfloat162float(__float2bfloat16(v03));
            const float h10 = __bfloat162float(__float2bfloat16(v10));
            const float h11 = __bfloat162float(__float2bfloat16(v11));
            const float h12 = __bfloat162float(__float2bfloat16(v12));
            const float h13 = __bfloat162float(__float2bfloat16(v13));
            const uint32_t ph0 = pack_bf16(v00, v01), ph1 = pack_bf16(v02, v03);
            const uint32_t ph2 = pack_bf16(v10, v11), ph3 = pack_bf16(v12, v13);
            const uint32_t pl0 = pack_bf16(v00 - h00, v01 - h01);
            const uint32_t pl1 = pack_bf16(v02 - h02, v03 - h03);
            const uint32_t pl2 = pack_bf16(v10 - h10, v11 - h11);
            const uint32_t pl3 = pack_bf16(v12 - h12, v13 - h13);

            const uint32_t vrow_h =
                sbase + (uint32_t)(VH + (kp * 16 + (lane & 15)) * AROW) * 2;
            const uint32_t vrow_l =
                sbase + (uint32_t)(VL + (kp * 16 + (lane & 15)) * AROW) * 2;
#pragma unroll
            for (int nt = 0; nt < 16; nt++) {
                uint32_t bh0, bh1, bl0, bl1;
                LDMAT_X2_T(bh0, bh1, vrow_h + nt * 16);
                LDMAT_X2_T(bl0, bl1, vrow_l + nt * 16);
                mma_bf16(o[nt], ph0, ph1, ph2, ph3, bh0, bh1);
                mma_bf16(o[nt], ph0, ph1, ph2, ph3, bl0, bl1);
                mma_bf16(o[nt], pl0, pl1, pl2, pl3, bh0, bh1);
            }
        }

        // V buffers consumed -> prefetch V(kt+1) (hidden behind next S+softmax)
        __syncthreads();
        if (kt < qt) {
            const int kn = (kt + 1) * 64;
            attn_load64(sbase, VH, g_vh + (size_t)kn * DM + h * DH, tid);
            attn_load64(sbase, VL, g_vl + (size_t)kn * DM + h * DH, tid);
            CP_COMMIT();
        }
    }

    const float inv0 = 1.f / l0, inv1 = 1.f / l1;
    const int r0 = q0 + wr + gg, r1 = r0 + 8;
    const int colb = h * DH + tg * 2;
#pragma unroll
    for (int nt = 0; nt < 16; nt++) {
        const int col = colb + nt * 8;
        const float f0 = o[nt][0] * inv0, f1 = o[nt][1] * inv0;
        const float f2 = o[nt][2] * inv1, f3 = o[nt][3] * inv1;
        const float h0 = __bfloat162float(__float2bfloat16(f0));
        const float h1 = __bfloat162float(__float2bfloat16(f1));
        const float h2 = __bfloat162float(__float2bfloat16(f2));
        const float h3 = __bfloat162float(__float2bfloat16(f3));
        *(uint32_t*)&g_ath[(size_t)r0 * DM + col] = pack_bf16(f0, f1);
        *(uint32_t*)&g_atl[(size_t)r0 * DM + col] = pack_bf16(f0 - h0, f1 - h1);
        *(uint32_t*)&g_ath[(size_t)r1 * DM + col] = pack_bf16(f2, f3);
        *(uint32_t*)&g_atl[(size_t)r1 * DM + col] = pack_bf16(f2 - h2, f3 - h3);
    }
}

// ===================== launcher ==============================================
extern "C" void kernel_launch(void* const* d_in, const int* in_sizes, int n_in,
                              void* d_out, int out_size) {
    const float* x    = (const float*)d_in[0];
    const float* w_ln = (const float*)d_in[1];
    const float* wq   = (const float*)d_in[2];
    const float* wk   = (const float*)d_in[3];
    const float* wv   = (const float*)d_in[4];
    const float* wo   = (const float*)d_in[5];
    const float* cosb = (const float*)d_in[6];
    const float* sinb = (const float*)d_in[7];
    float* out = (float*)d_out;

    (void)cudaFuncSetAttribute(qkv_gemm_kernel,
                               cudaFuncAttributeMaxDynamicSharedMemorySize, GEMM_SMEM);
    (void)cudaFuncSetAttribute(o_gemm_kernel,
                               cudaFuncAttributeMaxDynamicSharedMemorySize, GEMM_SMEM);
    (void)cudaFuncSetAttribute(attn_mma_kernel,
                               cudaFuncAttributeMaxDynamicSharedMemorySize, ATTN_SMEM);

    split_all_kernel<<<4 * 4096, 256>>>(wq, wk, wv, wo);
    rmsnorm_kernel<<<TT, 256>>>(x, w_ln);
    qkv_gemm_kernel<<<dim3(24, 16), 256, GEMM_SMEM>>>(cosb, sinb);
    attn_mma_kernel<<<dim3(TT / 64, NH), 128, ATTN_SMEM>>>();
    o_gemm_kernel<<<dim3(8, 16), 256, GEMM_SMEM>>>(out, x);
}

// round 15
// speedup vs baseline: 1.0057x; 1.0019x over previous
#include <cuda_runtime.h>
#include <cuda_bf16.h>
#include <cstdint>
#include <math.h>

#define TT 2048
#define DM 2048
#define NH 16
#define DH 128

// ===================== PTX helpers ==========================================
__device__ __forceinline__ uint32_t smem_u32(const void* p) {
    uint32_t a;
    asm("{ .reg .u64 t; cvta.to.shared.u64 t, %1; cvt.u32.u64 %0, t; }"
        : "=r"(a) : "l"(p));
    return a;
}

#define CPASYNC16(dst, src) \
    asm volatile("cp.async.cg.shared.global [%0], [%1], 16;" :: "r"(dst), "l"(src))
#define CP_COMMIT() asm volatile("cp.async.commit_group;" ::: "memory")
#define CP_WAIT0() asm volatile("cp.async.wait_group 0;" ::: "memory")
#define CP_WAIT1() asm volatile("cp.async.wait_group 1;" ::: "memory")

#define LDMAT_X4(r0, r1, r2, r3, addr) \
    asm volatile("ldmatrix.sync.aligned.m8n8.x4.shared.b16 {%0,%1,%2,%3}, [%4];" \
                 : "=r"(r0), "=r"(r1), "=r"(r2), "=r"(r3) : "r"(addr))
#define LDMAT_X2_T(b0, b1, addr) \
    asm volatile("ldmatrix.sync.aligned.m8n8.x2.trans.shared.b16 {%0,%1}, [%2];" \
                 : "=r"(b0), "=r"(b1) : "r"(addr))

__device__ __forceinline__ void mma_bf16(float* c, uint32_t a0, uint32_t a1,
                                         uint32_t a2, uint32_t a3,
                                         uint32_t b0, uint32_t b1) {
    asm volatile(
        "mma.sync.aligned.m16n8k16.row.col.f32.bf16.bf16.f32 "
        "{%0,%1,%2,%3}, {%4,%5,%6,%7}, {%8,%9}, {%0,%1,%2,%3};"
        : "+f"(c[0]), "+f"(c[1]), "+f"(c[2]), "+f"(c[3])
        : "r"(a0), "r"(a1), "r"(a2), "r"(a3), "r"(b0), "r"(b1));
}

__device__ __forceinline__ uint32_t pack_bf16(float a, float b) {
    __nv_bfloat162 t = __floats2bfloat162_rn(a, b);
    return *(uint32_t*)&t;
}

// ===================== scratch (static device globals) =======================
__device__ __nv_bfloat16 g_hh[(size_t)TT * DM], g_hl[(size_t)TT * DM];
__device__ __nv_bfloat16 g_ath[(size_t)TT * DM], g_atl[(size_t)TT * DM];
__device__ __nv_bfloat16 g_qh[(size_t)TT * DM], g_ql[(size_t)TT * DM];
__device__ __nv_bfloat16 g_kh[(size_t)TT * DM], g_kl[(size_t)TT * DM];
__device__ __nv_bfloat16 g_vh[(size_t)TT * DM], g_vl[(size_t)TT * DM];
__device__ __nv_bfloat16 g_wqh[(size_t)DM * DM], g_wql[(size_t)DM * DM];
__device__ __nv_bfloat16 g_wkh[(size_t)DM * DM], g_wkl[(size_t)DM * DM];
__device__ __nv_bfloat16 g_wvh[(size_t)DM * DM], g_wvl[(size_t)DM * DM];
__device__ __nv_bfloat16 g_woh[(size_t)DM * DM], g_wol[(size_t)DM * DM];

// ===================== fused split of all 4 weights ==========================
__global__ __launch_bounds__(256) void split_all_kernel(
    const float* __restrict__ wq, const float* __restrict__ wk,
    const float* __restrict__ wv, const float* __restrict__ wo) {
    const int w = blockIdx.x >> 12;
    const int blk = blockIdx.x & 4095;
    const float* X = (w == 0) ? wq : (w == 1) ? wk : (w == 2) ? wv : wo;
    __nv_bfloat16* Hi = (w == 0) ? g_wqh : (w == 1) ? g_wkh : (w == 2) ? g_wvh : g_woh;
    __nv_bfloat16* Lo = (w == 0) ? g_wql : (w == 1) ? g_wkl : (w == 2) ? g_wvl : g_wol;

    const int i = (blk * 256 + threadIdx.x) * 4;
    float4 v = *(const float4*)(X + i);
    float f[4] = {v.x, v.y, v.z, v.w};
    unsigned short hb[4], lb[4];
#pragma unroll
    for (int j = 0; j < 4; j++) {
        __nv_bfloat16 h = __float2bfloat16(f[j]);
        __nv_bfloat16 l = __float2bfloat16(f[j] - __bfloat162float(h));
        hb[j] = __bfloat16_as_ushort(h);
        lb[j] = __bfloat16_as_ushort(l);
    }
    uint2 hv, lv;
    hv.x = (uint32_t)hb[0] | ((uint32_t)hb[1] << 16);
    hv.y = (uint32_t)hb[2] | ((uint32_t)hb[3] << 16);
    lv.x = (uint32_t)lb[0] | ((uint32_t)lb[1] << 16);
    lv.y = (uint32_t)lb[2] | ((uint32_t)lb[3] << 16);
    *(uint2*)(Hi + i) = hv;
    *(uint2*)(Lo + i) = lv;
}

// ===================== RMSNorm (emits bf16 hi/lo) ============================
__global__ __launch_bounds__(256) void rmsnorm_kernel(const float* __restrict__ x,
                                                      const float* __restrict__ w) {
    __shared__ float red[256];
    const int row = blockIdx.x;
    const int tid = threadIdx.x;
    const float* xr = x + (size_t)row * DM;
    float s = 0.f;
    for (int i = tid; i < DM; i += 256) { float v = xr[i]; s += v * v; }
    red[tid] = s;
    __syncthreads();
    for (int o = 128; o > 0; o >>= 1) {
        if (tid < o) red[tid] += red[tid + o];
        __syncthreads();
    }
    const float inv = rsqrtf(red[0] / (float)DM + 1e-5f);
    __nv_bfloat16* hh = g_hh + (size_t)row * DM;
    __nv_bfloat16* hl = g_hl + (size_t)row * DM;
    for (int i = tid; i < DM; i += 256) {
        float y = w[i] * xr[i] * inv;
        __nv_bfloat16 h = __float2bfloat16(y);
        hh[i] = h;
        hl[i] = __float2bfloat16(y - __bfloat162float(h));
    }
}

// ===================== shared GEMM machinery =================================
// CTA tile 128(M) x 256(N), BK=32, 8 warps in 2(M)x4(N) -> warp tile 64x64.
#define SPAD 40
#define EA_L (128 * SPAD)        // elem offsets inside a stage
#define EB_H (256 * SPAD)
#define EB_L (512 * SPAD)
#define STG_E (768 * SPAD)       // stage elems
#define GEMM_SMEM (2 * STG_E * 2)  // 122880 bytes
#define SROW 132                 // fp32 epilogue staging row stride

__device__ __forceinline__ void gemm_load_stage(
    uint32_t sbase, int st,
    const __nv_bfloat16* Ah, const __nv_bfloat16* Al,
    const __nv_bfloat16* Bh, const __nv_bfloat16* Bl,
    int m0, int n0, int k0, int tid) {
    const uint32_t sb = sbase + (uint32_t)(st * STG_E) * 2;
    const __nv_bfloat16* pAh = Ah + (size_t)m0 * DM + k0;
    const __nv_bfloat16* pAl = Al + (size_t)m0 * DM + k0;
    const __nv_bfloat16* pBh = Bh + (size_t)n0 * DM + k0;
    const __nv_bfloat16* pBl = Bl + (size_t)n0 * DM + k0;
#pragma unroll
    for (int i = 0; i < 2; i++) {
        const int idx = i * 256 + tid;
        const int r = idx >> 2, c = idx & 3;
        CPASYNC16(sb + (uint32_t)(r * SPAD + c * 8) * 2, pAh + (size_t)r * DM + c * 8);
        CPASYNC16(sb + (uint32_t)(EA_L + r * SPAD + c * 8) * 2, pAl + (size_t)r * DM + c * 8);
    }
#pragma unroll
    for (int i = 0; i < 4; i++) {
        const int idx = i * 256 + tid;
        const int r = idx >> 2, c = idx & 3;
        CPASYNC16(sb + (uint32_t)(EB_H + r * SPAD + c * 8) * 2, pBh + (size_t)r * DM + c * 8);
        CPASYNC16(sb + (uint32_t)(EB_L + r * SPAD + c * 8) * 2, pBl + (size_t)r * DM + c * 8);
    }
}

__device__ __forceinline__ void gemm_mainloop(
    uint32_t sbase, const __nv_bfloat16* Ah, const __nv_bfloat16* Al,
    const __nv_bfloat16* Bh, const __nv_bfloat16* Bl,
    int m0, int n0, int tid, int wm, int wn,
    int a_row, int a_colp, int b_row, int b_ntp, int b_colp,
    float acc[4][8][4]) {
    gemm_load_stage(sbase, 0, Ah, Al, Bh, Bl, m0, n0, 0, tid);
    CP_COMMIT();

    for (int c = 0; c < DM / 32; c++) {
        CP_WAIT0();
        __syncthreads();
        if (c + 1 < DM / 32) {
            gemm_load_stage(sbase, (c + 1) & 1, Ah, Al, Bh, Bl, m0, n0, (c + 1) * 32, tid);
            CP_COMMIT();
        }
        const uint32_t stg = sbase + (uint32_t)((c & 1) * STG_E) * 2;

#pragma unroll
        for (int ks = 0; ks < 32; ks += 16) {
            uint32_t ah[4][4], bh[8][2];
#pragma unroll
            for (int mt = 0; mt < 4; mt++) {
                const uint32_t ra =
                    (uint32_t)((wm + mt * 16 + a_row) * SPAD + ks + a_colp) * 2;
                LDMAT_X4(ah[mt][0], ah[mt][1], ah[mt][2], ah[mt][3], stg + ra);
            }
#pragma unroll
            for (int np = 0; np < 4; np++) {
                const uint32_t rb =
                    (uint32_t)(EB_H + (wn + np * 16 + b_ntp + b_row) * SPAD + ks + b_colp) * 2;
                LDMAT_X4(bh[np * 2][0], bh[np * 2 + 1][0],
                         bh[np * 2][1], bh[np * 2 + 1][1], stg + rb);
            }
#pragma unroll
            for (int mt = 0; mt < 4; mt++)
#pragma unroll
                for (int nt = 0; nt < 8; nt++)
                    mma_bf16(acc[mt][nt], ah[mt][0], ah[mt][1], ah[mt][2], ah[mt][3],
                             bh[nt][0], bh[nt][1]);
            {
                uint32_t bl[8][2];
#pragma unroll
                for (int np = 0; np < 4; np++) {
                    const uint32_t rb =
                        (uint32_t)(EB_L + (wn + np * 16 + b_ntp + b_row) * SPAD + ks + b_colp) * 2;
                    LDMAT_X4(bl[np * 2][0], bl[np * 2 + 1][0],
                             bl[np * 2][1], bl[np * 2 + 1][1], stg + rb);
                }
#pragma unroll
                for (int mt = 0; mt < 4; mt++)
#pragma unroll
                    for (int nt = 0; nt < 8; nt++)
                        mma_bf16(acc[mt][nt], ah[mt][0], ah[mt][1], ah[mt][2], ah[mt][3],
                                 bl[nt][0], bl[nt][1]);
            }
            {
                uint32_t al[4][4];
#pragma unroll
                for (int mt = 0; mt < 4; mt++) {
                    const uint32_t ra =
                        (uint32_t)(EA_L + (wm + mt * 16 + a_row) * SPAD + ks + a_colp) * 2;
                    LDMAT_X4(al[mt][0], al[mt][1], al[mt][2], al[mt][3], stg + ra);
                }
#pragma unroll
                for (int mt = 0; mt < 4; mt++)
#pragma unroll
                    for (int nt = 0; nt < 8; nt++)
                        mma_bf16(acc[mt][nt], al[mt][0], al[mt][1], al[mt][2], al[mt][3],
                                 bh[nt][0], bh[nt][1]);
            }
        }
    }
    __syncthreads();  // mainloop smem dead; epilogue may reuse it
}

// ===================== fused QKV projection + RoPE + split ===================
// grid (24, 16): blockIdx.x -> {Q: 0-7, K: 8-15, V: 16-23}; 256-col tile = 2 heads.
__global__ __launch_bounds__(256) void qkv_gemm_kernel(const float* __restrict__ cosb,
                                                       const float* __restrict__ sinb) {
    extern __shared__ __nv_bfloat16 dynsm[];
    const uint32_t sbase = smem_u32(dynsm);
    const int tid = threadIdx.x;
    const int wid = tid >> 5, lane = tid & 31;
    const int gg = lane >> 2, tg = lane & 3;
    const int wm = (wid >> 2) * 64, wn = (wid & 3) * 64;
    const int sel = blockIdx.x >> 3;       // 0=Q 1=K 2=V
    const int nblk = blockIdx.x & 7;
    const int n0 = nblk * 256;
    const int m0 = blockIdx.y * 128;

    const int a_row = (lane & 7) + ((lane >> 3) & 1) * 8;
    const int a_colp = (lane >> 4) * 8;
    const int b_row = lane & 7;
    const int b_ntp = ((lane >> 3) & 1) * 8;
    const int b_colp = ((lane >> 4) & 1) * 8;

    const __nv_bfloat16* Bh = (sel == 0) ? g_wqh : (sel == 1) ? g_wkh : g_wvh;
    const __nv_bfloat16* Bl = (sel == 0) ? g_wql : (sel == 1) ? g_wkl : g_wvl;

    float acc[4][8][4];
#pragma unroll
    for (int mt = 0; mt < 4; mt++)
#pragma unroll
        for (int nt = 0; nt < 8; nt++)
#pragma unroll
            for (int j = 0; j < 4; j++) acc[mt][nt][j] = 0.f;

    gemm_mainloop(sbase, g_hh, g_hl, Bh, Bl, m0, n0, tid, wm, wn,
                  a_row, a_colp, b_row, b_ntp, b_colp, acc);

    if (sel == 2) {
#pragma unroll
        for (int mt = 0; mt < 4; mt++) {
            const int mA = m0 + wm + mt * 16 + gg;
            const int mB = mA + 8;
#pragma unroll
            for (int nt = 0; nt < 8; nt++) {
                const int n = n0 + wn + nt * 8 + tg * 2;
                const float v0 = acc[mt][nt][0], v1 = acc[mt][nt][1];
                const float v2 = acc[mt][nt][2], v3 = acc[mt][nt][3];
                const float h0 = __bfloat162float(__float2bfloat16(v0));
                const float h1 = __bfloat162float(__float2bfloat16(v1));
                const float h2 = __bfloat162float(__float2bfloat16(v2));
                const float h3 = __bfloat162float(__float2bfloat16(v3));
                *(uint32_t*)&g_vh[(size_t)mA * DM + n] = pack_bf16(v0, v1);
                *(uint32_t*)&g_vl[(size_t)mA * DM + n] = pack_bf16(v0 - h0, v1 - h1);
                *(uint32_t*)&g_vh[(size_t)mB * DM + n] = pack_bf16(v2, v3);
                *(uint32_t*)&g_vl[(size_t)mB * DM + n] = pack_bf16(v2 - h2, v3 - h3);
            }
        }
        return;
    }

    // Q/K: RoPE + hi/lo split in two 128-col passes through reused stage smem
    float* S = (float*)dynsm;
    __nv_bfloat16* Hi = (sel == 0) ? g_qh : g_kh;
    __nv_bfloat16* Lo = (sel == 0) ? g_ql : g_kl;

#pragma unroll 1
    for (int half = 0; half < 2; half++) {
        if (((wid & 3) >> 1) == half) {
            const int wnn = (wid & 1) * 64;
#pragma unroll
            for (int mt = 0; mt < 4; mt++) {
                const int rA = wm + mt * 16 + gg, rB = rA + 8;
#pragma unroll
                for (int nt = 0; nt < 8; nt++) {
                    const int n = wnn + nt * 8 + tg * 2;
                    S[rA * SROW + n] = acc[mt][nt][0];
                    S[rA * SROW + n + 1] = acc[mt][nt][1];
                    S[rB * SROW + n] = acc[mt][nt][2];
                    S[rB * SROW + n + 1] = acc[mt][nt][3];
                }
            }
        }
        __syncthreads();

        const int head = nblk * 2 + half;
#pragma unroll
        for (int i = 0; i < 8; i++) {
            const int idx = i * 256 + tid;
            const int r = idx >> 4;
            const int c = (idx & 15) * 4;
            const int t = m0 + r;
            float4 x0 = *(const float4*)&S[r * SROW + c];
            float4 x1 = *(const float4*)&S[r * SROW + c + 64];
            float4 c0 = *(const float4*)(cosb + t * DH + c);
            float4 s0 = *(const float4*)(sinb + t * DH + c);
            float4 c1 = *(const float4*)(cosb + t * DH + c + 64);
            float4 s1 = *(const float4*)(sinb + t * DH + c + 64);

            float qa[4], qb[4];
            qa[0] = x0.x * c0.x - x1.x * s0.x; qb[0] = x1.x * c1.x + x0.x * s1.x;
            qa[1] = x0.y * c0.y - x1.y * s0.y; qb[1] = x1.y * c1.y + x0.y * s1.y;
            qa[2] = x0.z * c0.z - x1.z * s0.z; qb[2] = x1.z * c1.z + x0.z * s1.z;
            qa[3] = x0.w * c0.w - x1.w * s0.w; qb[3] = x1.w * c1.w + x0.w * s1.w;

            uint2 hA, lA, hB, lB;
            {
                float ha0 = __bfloat162float(__float2bfloat16(qa[0]));
                float ha1 = __bfloat162float(__float2bfloat16(qa[1]));
                float ha2 = __bfloat162float(__float2bfloat16(qa[2]));
                float ha3 = __bfloat162float(__float2bfloat16(qa[3]));
                hA.x = pack_bf16(qa[0], qa[1]); hA.y = pack_bf16(qa[2], qa[3]);
                lA.x = pack_bf16(qa[0] - ha0, qa[1] - ha1);
                lA.y = pack_bf16(qa[2] - ha2, qa[3] - ha3);
                float hb0 = __bfloat162float(__float2bfloat16(qb[0]));
                float hb1 = __bfloat162float(__float2bfloat16(qb[1]));
                float hb2 = __bfloat162float(__float2bfloat16(qb[2]));
                float hb3 = __bfloat162float(__float2bfloat16(qb[3]));
                hB.x = pack_bf16(qb[0], qb[1]); hB.y = pack_bf16(qb[2], qb[3]);
                lB.x = pack_bf16(qb[0] - hb0, qb[1] - hb1);
                lB.y = pack_bf16(qb[2] - hb2, qb[3] - hb3);
            }
            const size_t base = (size_t)t * DM + head * DH + c;
            *(uint2*)&Hi[base] = hA;      *(uint2*)&Lo[base] = lA;
            *(uint2*)&Hi[base + 64] = hB; *(uint2*)&Lo[base + 64] = lB;
        }
        __syncthreads();
    }
}

// ===================== O projection GEMM (+ residual) ========================
__global__ __launch_bounds__(256) void o_gemm_kernel(float* __restrict__ C,
                                                     const float* __restrict__ R) {
    extern __shared__ __nv_bfloat16 dynsm[];
    const uint32_t sbase = smem_u32(dynsm);
    const int tid = threadIdx.x;
    const int wid = tid >> 5, lane = tid & 31;
    const int gg = lane >> 2, tg = lane & 3;
    const int wm = (wid >> 2) * 64, wn = (wid & 3) * 64;
    const int m0 = blockIdx.y * 128, n0 = blockIdx.x * 256;

    const int a_row = (lane & 7) + ((lane >> 3) & 1) * 8;
    const int a_colp = (lane >> 4) * 8;
    const int b_row = lane & 7;
    const int b_ntp = ((lane >> 3) & 1) * 8;
    const int b_colp = ((lane >> 4) & 1) * 8;

    float acc[4][8][4];
#pragma unroll
    for (int mt = 0; mt < 4; mt++)
#pragma unroll
        for (int nt = 0; nt < 8; nt++)
#pragma unroll
            for (int j = 0; j < 4; j++) acc[mt][nt][j] = 0.f;

    gemm_mainloop(sbase, g_ath, g_atl, g_woh, g_wol, m0, n0, tid, wm, wn,
                  a_row, a_colp, b_row, b_ntp, b_colp, acc);

#pragma unroll
    for (int mt = 0; mt < 4; mt++) {
        const int mA = m0 + wm + mt * 16 + gg;
        const int mB = mA + 8;
#pragma unroll
        for (int nt = 0; nt < 8; nt++) {
            const int n = n0 + wn + nt * 8 + tg * 2;
            float v0 = acc[mt][nt][0], v1 = acc[mt][nt][1];
            float v2 = acc[mt][nt][2], v3 = acc[mt][nt][3];
            float2 r0 = *(const float2*)(R + (size_t)mA * DM + n);
            float2 r1 = *(const float2*)(R + (size_t)mB * DM + n);
            v0 += r0.x; v1 += r0.y; v2 += r1.x; v3 += r1.y;
            *(float2*)(C + (size_t)mA * DM + n) = make_float2(v0, v1);
            *(float2*)(C + (size_t)mB * DM + n) = make_float2(v2, v3);
        }
    }
}

// ===================== flash attention: prefetch + partial Q hoist ===========
#define AROW 136
#define ATILE (64 * AROW)
#define ATTN_SMEM (6 * ATILE * 2)  // 104448 bytes -> 2 CTAs/SM

__device__ __forceinline__ void attn_load64(uint32_t sbase, int elem_off,
                                            const __nv_bfloat16* g, int tid) {
#pragma unroll
    for (int t = 0; t < 8; t++) {
        const int idx = t * 128 + tid;
        const int r = idx >> 4, c = idx & 15;
        const uint32_t dst = sbase + (uint32_t)(elem_off + r * AROW + c * 8) * 2;
        CPASYNC16(dst, g + (size_t)r * DM + c * 8);
    }
}

__global__ __launch_bounds__(128) void attn_mma_kernel() {
    extern __shared__ __nv_bfloat16 dynsm[];
    const uint32_t sbase = smem_u32(dynsm);
    const int QH = 0, QL = ATILE, KH = 2 * ATILE, KL = 3 * ATILE,
              VH = 4 * ATILE, VL = 5 * ATILE;
    const int qt = (int)gridDim.x - 1 - (int)blockIdx.x;  // long tiles first
    const int h = blockIdx.y;
    const int tid = threadIdx.x, wid = tid >> 5, lane = tid & 31;
    const int gg = lane >> 2, tg = lane & 3;
    const int q0 = qt * 64, wr = wid * 16;
    const float scale = 0.08838834764831845f;

    const int a_row = (lane & 7) + ((lane >> 3) & 1) * 8;
    const int a_colp = (lane >> 4) * 8;
    const int b_row = lane & 7;
    const int b_ntp = ((lane >> 3) & 1) * 8;
    const int b_colp = ((lane >> 4) & 1) * 8;

    // prologue: Q tiles
    attn_load64(sbase, QH, g_qh + (size_t)q0 * DM + h * DH, tid);
    attn_load64(sbase, QL, g_ql + (size_t)q0 * DM + h * DH, tid);
    CP_COMMIT();
    CP_WAIT0();
    __syncthreads();

    // partial hoist: loop-invariant Q-hi fragments into registers (+32 regs)
    uint32_t qh_r[8][4];
#pragma unroll
    for (int ks = 0; ks < 8; ks++) {
        const uint32_t ra = (uint32_t)((wr + a_row) * AROW + ks * 16 + a_colp) * 2;
        LDMAT_X4(qh_r[ks][0], qh_r[ks][1], qh_r[ks][2], qh_r[ks][3], sbase + QH * 2 + ra);
    }

    // K(0)+V(0) prefetch
    attn_load64(sbase, KH, g_kh + (size_t)0 + h * DH, tid);
    attn_load64(sbase, KL, g_kl + (size_t)0 + h * DH, tid);
    CP_COMMIT();
    attn_load64(sbase, VH, g_vh + (size_t)0 + h * DH, tid);
    attn_load64(sbase, VL, g_vl + (size_t)0 + h * DH, tid);
    CP_COMMIT();

    float m0 = -1e30f, m1 = -1e30f, l0 = 0.f, l1 = 0.f;
    float o[16][4];
#pragma unroll
    for (int nt = 0; nt < 16; nt++)
#pragma unroll
        for (int j = 0; j < 4; j++) o[nt][j] = 0.f;

    for (int kt = 0; kt <= qt; kt++) {
        // wait K(kt): pending groups = {K(kt), V(kt)}
        CP_WAIT1();
        __syncthreads();

        // ---- S = Q K^T (split 3-product; Q-hi from registers) ----
        float s[8][4];
#pragma unroll
        for (int nt = 0; nt < 8; nt++)
#pragma unroll
            for (int j = 0; j < 4; j++) s[nt][j] = 0.f;

#pragma unroll
        for (int ks = 0; ks < 8; ks++) {
            const int kk = ks * 16;
            uint32_t al[4], bh[8][2], bl[8][2];
            const uint32_t ra = (uint32_t)((wr + a_row) * AROW + kk + a_colp) * 2;
            LDMAT_X4(al[0], al[1], al[2], al[3], sbase + QL * 2 + ra);
#pragma unroll
            for (int np = 0; np < 4; np++) {
                const uint32_t rb =
                    (uint32_t)((np * 16 + b_ntp + b_row) * AROW + kk + b_colp) * 2;
                LDMAT_X4(bh[np * 2][0], bh[np * 2 + 1][0],
                         bh[np * 2][1], bh[np * 2 + 1][1], sbase + KH * 2 + rb);
                LDMAT_X4(bl[np * 2][0], bl[np * 2 + 1][0],
                         bl[np * 2][1], bl[np * 2 + 1][1], sbase + KL * 2 + rb);
            }
#pragma unroll
            for (int nt = 0; nt < 8; nt++) {
                mma_bf16(s[nt], qh_r[ks][0], qh_r[ks][1], qh_r[ks][2], qh_r[ks][3],
                         bh[nt][0], bh[nt][1]);
                mma_bf16(s[nt], qh_r[ks][0], qh_r[ks][1], qh_r[ks][2], qh_r[ks][3],
                         bl[nt][0], bl[nt][1]);
                mma_bf16(s[nt], al[0], al[1], al[2], al[3], bh[nt][0], bh[nt][1]);
            }
        }

        // K buffers consumed -> prefetch K(kt+1) (hidden behind softmax + PV)
        __syncthreads();
        if (kt < qt) {
            const int kn = (kt + 1) * 64;
            attn_load64(sbase, KH, g_kh + (size_t)kn * DM + h * DH, tid);
            attn_load64(sbase, KL, g_kl + (size_t)kn * DM + h * DH, tid);
            CP_COMMIT();
        }

        // ---- scale + causal mask ----
        if (kt == qt) {
            const int r0i = wr + gg, r1i = r0i + 8;
#pragma unroll
            for (int nt = 0; nt < 8; nt++) {
                const int c0 = nt * 8 + tg * 2, c1 = c0 + 1;
                s[nt][0] = (c0 > r0i) ? -1e30f : s[nt][0] * scale;
                s[nt][1] = (c1 > r0i) ? -1e30f : s[nt][1] * scale;
                s[nt][2] = (c0 > r1i) ? -1e30f : s[nt][2] * scale;
                s[nt][3] = (c1 > r1i) ? -1e30f : s[nt][3] * scale;
            }
        } else {
#pragma unroll
            for (int nt = 0; nt < 8; nt++)
#pragma unroll
                for (int j = 0; j < 4; j++) s[nt][j] *= scale;
        }

        // ---- online softmax ----
        float mx0 = -1e30f, mx1 = -1e30f;
#pragma unroll
        for (int nt = 0; nt < 8; nt++) {
            mx0 = fmaxf(mx0, fmaxf(s[nt][0], s[nt][1]));
            mx1 = fmaxf(mx1, fmaxf(s[nt][2], s[nt][3]));
        }
        mx0 = fmaxf(mx0, __shfl_xor_sync(0xffffffffu, mx0, 1));
        mx0 = fmaxf(mx0, __shfl_xor_sync(0xffffffffu, mx0, 2));
        mx1 = fmaxf(mx1, __shfl_xor_sync(0xffffffffu, mx1, 1));
        mx1 = fmaxf(mx1, __shfl_xor_sync(0xffffffffu, mx1, 2));
        const float mn0 = fmaxf(m0, mx0), mn1 = fmaxf(m1, mx1);
        const float a0 = __expf(m0 - mn0), a1 = __expf(m1 - mn1);
        m0 = mn0; m1 = mn1;
        float rs0 = 0.f, rs1 = 0.f;
#pragma unroll
        for (int nt = 0; nt < 8; nt++) {
            s[nt][0] = __expf(s[nt][0] - mn0); rs0 += s[nt][0];
            s[nt][1] = __expf(s[nt][1] - mn0); rs0 += s[nt][1];
            s[nt][2] = __expf(s[nt][2] - mn1); rs1 += s[nt][2];
            s[nt][3] = __expf(s[nt][3] - mn1); rs1 += s[nt][3];
        }
        rs0 += __shfl_xor_sync(0xffffffffu, rs0, 1);
        rs0 += __shfl_xor_sync(0xffffffffu, rs0, 2);
        rs1 += __shfl_xor_sync(0xffffffffu, rs1, 1);
        rs1 += __shfl_xor_sync(0xffffffffu, rs1, 2);
        l0 = l0 * a0 + rs0;
        l1 = l1 * a1 + rs1;
#pragma unroll
        for (int nt = 0; nt < 16; nt++) {
            o[nt][0] *= a0; o[nt][1] *= a0;
            o[nt][2] *= a1; o[nt][3] *= a1;
        }

        // wait V(kt): pending = {V(kt)} (+ K(kt+1) if committed)
        if (kt < qt) CP_WAIT1(); else CP_WAIT0();
        __syncthreads();

        // ---- O += P V (split 3-product; V^T via ldmatrix.trans) ----
#pragma unroll
        for (int kp = 0; kp < 4; kp++) {
            const int j0 = kp * 2, j1 = j0 + 1;
            const float v00 = s[j0][0], v01 = s[j0][1], v02 = s[j0][2], v03 = s[j0][3];
            const float v10 = s[j1][0], v11 = s[j1][1], v12 = s[j1][2], v13 = s[j1][3];
            const float h00 = __bfloat162float(__float2bfloat16(v00));
            const float h01 = __bfloat162float(__float2bfloat16(v01));
            const float h02 = __bfloat162float(__float2bfloat16(v02));
            const float h03 = __bfloat162float(__float2bfloat16(v03));
            const float h10 = __bfloat162float(__float2bfloat16(v10));
            const float h11 = __bfloat162float(__float2bfloat16(v11));
            const float h12 = __bfloat162float(__float2bfloat16(v12));
            const float h13 = __bfloat162float(__float2bfloat16(v13));
            const uint32_t ph0 = pack_bf16(v00, v01), ph1 = pack_bf16(v02, v03);
            const uint32_t ph2 = pack_bf16(v10, v11), ph3 = pack_bf16(v12, v13);
            const uint32_t pl0 = pack_bf16(v00 - h00, v01 - h01);
            const uint32_t pl1 = pack_bf16(v02 - h02, v03 - h03);
            const uint32_t pl2 = pack_bf16(v10 - h10, v11 - h11);
            const uint32_t pl3 = pack_bf16(v12 - h12, v13 - h13);

            const uint32_t vrow_h =
                sbase + (uint32_t)(VH + (kp * 16 + (lane & 15)) * AROW) * 2;
            const uint32_t vrow_l =
                sbase + (uint32_t)(VL + (kp * 16 + (lane & 15)) * AROW) * 2;
#pragma unroll
            for (int nt = 0; nt < 16; nt++) {
                uint32_t bh0, bh1, bl0, bl1;
                LDMAT_X2_T(bh0, bh1, vrow_h + nt * 16);
                LDMAT_X2_T(bl0, bl1, vrow_l + nt * 16);
                mma_bf16(o[nt], ph0, ph1, ph2, ph3, bh0, bh1);
                mma_bf16(o[nt], ph0, ph1, ph2, ph3, bl0, bl1);
                mma_bf16(o[nt], pl0, pl1, pl2, pl3, bh0, bh1);
            }
        }

        // V buffers consumed -> prefetch V(kt+1) (hidden behind next S+softmax)
        __syncthreads();
        if (kt < qt) {
            const int kn = (kt + 1) * 64;
            attn_load64(sbase, VH, g_vh + (size_t)kn * DM + h * DH, tid);
            attn_load64(sbase, VL, g_vl + (size_t)kn * DM + h * DH, tid);
            CP_COMMIT();
        }
    }

    const float inv0 = 1.f / l0, inv1 = 1.f / l1;
    const int r0 = q0 + wr + gg, r1 = r0 + 8;
    const int colb = h * DH + tg * 2;
#pragma unroll
    for (int nt = 0; nt < 16; nt++) {
        const int col = colb + nt * 8;
        const float f0 = o[nt][0] * inv0, f1 = o[nt][1] * inv0;
        const float f2 = o[nt][2] * inv1, f3 = o[nt][3] * inv1;
        const float h0 = __bfloat162float(__float2bfloat16(f0));
        const float h1 = __bfloat162float(__float2bfloat16(f1));
        const float h2 = __bfloat162float(__float2bfloat16(f2));
        const float h3 = __bfloat162float(__float2bfloat16(f3));
        *(uint32_t*)&g_ath[(size_t)r0 * DM + col] = pack_bf16(f0, f1);
        *(uint32_t*)&g_atl[(size_t)r0 * DM + col] = pack_bf16(f0 - h0, f1 - h1);
        *(uint32_t*)&g_ath[(size_t)r1 * DM + col] = pack_bf16(f2, f3);
        *(uint32_t*)&g_atl[(size_t)r1 * DM + col] = pack_bf16(f2 - h2, f3 - h3);
    }
}

// ===================== launcher ==============================================
extern "C" void kernel_launch(void* const* d_in, const int* in_sizes, int n_in,
                              void* d_out, int out_size) {
    const float* x    = (const float*)d_in[0];
    const float* w_ln = (const float*)d_in[1];
    const float* wq   = (const float*)d_in[2];
    const float* wk   = (const float*)d_in[3];
    const float* wv   = (const float*)d_in[4];
    const float* wo   = (const float*)d_in[5];
    const float* cosb = (const float*)d_in[6];
    const float* sinb = (const float*)d_in[7];
    float* out = (float*)d_out;

    (void)cudaFuncSetAttribute(qkv_gemm_kernel,
                               cudaFuncAttributeMaxDynamicSharedMemorySize, GEMM_SMEM);
    (void)cudaFuncSetAttribute(o_gemm_kernel,
                               cudaFuncAttributeMaxDynamicSharedMemorySize, GEMM_SMEM);
    (void)cudaFuncSetAttribute(attn_mma_kernel,
                               cudaFuncAttributeMaxDynamicSharedMemorySize, ATTN_SMEM);

    split_all_kernel<<<4 * 4096, 256>>>(wq, wk, wv, wo);
    rmsnorm_kernel<<<TT, 256>>>(x, w_ln);
    qkv_gemm_kernel<<<dim3(24, 16), 256, GEMM_SMEM>>>(cosb, sinb);
    attn_mma_kernel<<<dim3(TT / 64, NH), 128, ATTN_SMEM>>>();
    o_gemm_kernel<<<dim3(8, 16), 256, GEMM_SMEM>>>(out, x);
}